// round 2
// baseline (speedup 1.0000x reference)
#include <cuda_runtime.h>
#include <math.h>

#define NSITE 10

struct SM {
    float mps[8512];      // boundary-MPS working tensors; slots: j0:64, j1-8:1024 ea, j9:256
    float small[640];     // compressed MPS (<=4x4x4 per site), 64 per site
    float botS[640];      // saved bottom-half compressed MPS
    float tbuf[256];      // staged peps site slice [v][w][il][ic]
    float scratch[3072];  // right sweep: Acm(1024)|Qcm(1024)|work(1024); left sweep: m(256)|G(256)|U(256)
    float sv[64];         // s*vt carry, stride 16
    float Rdiag[16];
    float tau[16];
    float csC[8], csS[8];
    float Ebuf[16], Ebuf2[16];
    float bc0;
    float logn;
    int   prI[8], prJ[8];
    int   kidx[4];
    int   L[NSITE], R[NSITE];     // big dims (phys always 4)
    int   sL[NSITE], sR[NSITE];   // small dims
    int   bL[NSITE], bR[NSITE];   // saved bottom dims
    int   xr[100];
};

__device__ __forceinline__ int mpsOff(int j) {
    return (j == 0) ? 0 : ((j == 9) ? 8256 : (64 + (j - 1) * 1024));
}

__device__ __forceinline__ float wsum(float v) {
    #pragma unroll
    for (int o = 16; o > 0; o >>= 1) v += __shfl_xor_sync(0xffffffffu, v, o);
    return v;
}

// Initialize boundary MPS from row 0 (bottom, phys=w) or row 9 (top, phys=v).
__device__ void initRow(SM* s, const float* __restrict__ peps, int i, int lane, bool top) {
    for (int j = 0; j < NSITE; j++) {
        int L2 = (j == 0) ? 1 : 4, C2 = (j == 9) ? 1 : 4;
        int xp = s->xr[i * 10 + j];
        const float* base = peps + (size_t)(i * 10 + j) * 512;
        int tot = L2 * C2 * 4;
        for (int e = lane; e < tot; e += 32) {
            int ph = e & 3, rest = e >> 2;
            int ic = rest % C2, il = rest / C2;
            int v = top ? ph : 0;
            int w = top ? 0 : ph;
            s->small[j * 64 + e] = base[((((v * 4 + w) * 4 + il) * 4 + ic)) * 2 + xp];
        }
        if (lane == 0) { s->sL[j] = L2; s->sR[j] = C2; }
    }
    __syncwarp();
}

// Absorb PEPS row i into compressed MPS -> big tensors in mps[].
// bottom: out[(a*L2+il),(b*C2+ic),w] = sum_v m[a,b,v] t[v,w,il,ic]
// top:    out[(a*L2+il),(b*C2+ic),v] = sum_w m[a,b,w] t[v,w,il,ic]
__device__ void absorbRow(SM* s, const float* __restrict__ peps, int i, int lane, bool top) {
    for (int j = 0; j < NSITE; j++) {
        int L2 = (j == 0) ? 1 : 4, C2 = (j == 9) ? 1 : 4;
        int A = s->sL[j], Bb = s->sR[j];
        int xp = s->xr[i * 10 + j];
        const float* base = peps + (size_t)(i * 10 + j) * 512;
        int nt = 16 * L2 * C2;
        for (int e = lane; e < nt; e += 32) {
            int ic = e % C2; int r1 = e / C2;
            int il = r1 % L2; int vw = r1 / L2;
            s->tbuf[e] = base[((vw * 4 + il) * 4 + ic) * 2 + xp];
        }
        __syncwarp();
        int Ln = A * L2, Rn = Bb * C2, tot = Ln * Rn * 4;
        float* dst = s->mps + mpsOff(j);
        const float* sm = s->small + j * 64;
        for (int e = lane; e < tot; e += 32) {
            int ph = e & 3; int rest = e >> 2;
            int col = rest % Rn; int row = rest / Rn;
            int a = row / L2, il = row % L2;
            int bb = col / C2, ic = col % C2;
            const float* mr = sm + (a * Bb + bb) * 4;
            float acc = 0.f;
            if (!top) {
                #pragma unroll
                for (int v = 0; v < 4; v++)
                    acc += mr[v] * s->tbuf[((v * 4 + ph) * L2 + il) * C2 + ic];
            } else {
                #pragma unroll
                for (int w = 0; w < 4; w++)
                    acc += mr[w] * s->tbuf[((ph * 4 + w) * L2 + il) * C2 + ic];
            }
            dst[e] = acc;
        }
        if (lane == 0) { s->L[j] = Ln; s->R[j] = Rn; }
        __syncwarp();
    }
}

// Right-canonize j=9..1 via Householder LQ (QR of M^T). Gauge-equivalent to
// the reference's SVD right-canonization (amplitude invariant).
__device__ void rightSweep(SM* s, int lane) {
    float* Acm = s->scratch;             // [col<=16][row<=64] column-major, col stride 64
    float* Qcm = s->scratch + 1024;
    float* work = s->scratch + 2048;
    for (int j = 9; j >= 1; j--) {
        int l = s->L[j], rd = s->R[j] * 4;
        int k = (l < rd) ? l : rd;
        float* M = s->mps + mpsOff(j);
        // A = M^T (rd x l): column c of A = row c of M
        for (int e = lane; e < l * rd; e += 32) {
            int cc = e / rd, rr = e % rd;
            Acm[cc * 64 + rr] = M[cc * rd + rr];
        }
        __syncwarp();
        // Householder QR of A
        for (int c = 0; c < k; c++) {
            float sg = 0.f;
            for (int rr = c + lane; rr < rd; rr += 32) { float t = Acm[c * 64 + rr]; sg += t * t; }
            sg = wsum(sg);
            if (lane == 0) {
                float alpha = Acm[c * 64 + c];
                float nrm = sqrtf(sg);
                if (nrm < 1e-30f) { s->Rdiag[c] = 0.f; s->tau[c] = 0.f; s->bc0 = 0.f; }
                else {
                    float sn = (alpha >= 0.f) ? 1.f : -1.f;
                    float v0 = alpha + sn * nrm;
                    s->Rdiag[c] = -sn * nrm;
                    s->tau[c] = v0 / (sn * nrm);
                    s->bc0 = 1.f / v0;
                }
            }
            __syncwarp();
            float iv = s->bc0;
            for (int rr = c + lane; rr < rd; rr += 32)
                if (rr > c) Acm[c * 64 + rr] *= iv;
            float tc = s->tau[c];
            for (int c2 = c + 1; c2 < l; c2++) {
                float d = 0.f;
                for (int rr = c + lane; rr < rd; rr += 32) {
                    float vv = (rr == c) ? 1.f : Acm[c * 64 + rr];
                    d += vv * Acm[c2 * 64 + rr];
                }
                d = wsum(d); float w = tc * d;
                for (int rr = c + lane; rr < rd; rr += 32) {
                    float vv = (rr == c) ? 1.f : Acm[c * 64 + rr];
                    Acm[c2 * 64 + rr] -= w * vv;
                }
            }
            __syncwarp();
        }
        // Form Q (rd x k) by backward accumulation
        for (int e = lane; e < k * 64; e += 32) Qcm[e] = 0.f;
        __syncwarp();
        if (lane < k) Qcm[lane * 64 + lane] = 1.f;
        __syncwarp();
        for (int c = k - 1; c >= 0; c--) {
            float tc = s->tau[c];
            for (int c2 = c; c2 < k; c2++) {
                float d = 0.f;
                for (int rr = c + lane; rr < rd; rr += 32) {
                    float vv = (rr == c) ? 1.f : Acm[c * 64 + rr];
                    d += vv * Qcm[c2 * 64 + rr];
                }
                d = wsum(d); float w = tc * d;
                for (int rr = c + lane; rr < rd; rr += 32) {
                    float vv = (rr == c) ? 1.f : Acm[c * 64 + rr];
                    Qcm[c2 * 64 + rr] -= w * vv;
                }
            }
            __syncwarp();
        }
        // mps[j] <- Q^T (k x rd)
        for (int e = lane; e < k * rd; e += 32)
            M[e] = Qcm[(e / rd) * 64 + (e % rd)];
        // mps[j-1] <- mps[j-1] * R^T  (contract right bond l -> k)
        int A2 = s->L[j - 1];
        float* P = s->mps + mpsOff(j - 1);
        int totw = A2 * k * 4;
        __syncwarp();
        for (int e = lane; e < totw; e += 32) {
            int d4 = e & 3; int rest = e >> 2;
            int kk = rest % k; int a = rest / k;
            float acc = 0.f;
            for (int ll = kk; ll < l; ll++) {
                float rv = (ll == kk) ? s->Rdiag[kk] : Acm[ll * 64 + kk];
                acc += P[(a * l + ll) * 4 + d4] * rv;
            }
            work[e] = acc;
        }
        __syncwarp();
        for (int e = lane; e < totw; e += 32) P[e] = work[e];
        if (lane == 0) { s->L[j] = k; s->R[j - 1] = k; }
        __syncwarp();
    }
}

// Parallel round-robin cyclic Jacobi on G (nn x nn), accumulating U.
__device__ void jacobi(SM* s, int lane, int nn) {
    float* G = s->scratch + 256;
    float* U = s->scratch + 512;
    int np = nn >> 1;
    int rounds = nn - 1;
    int nsw = (nn == 16) ? 7 : 5;
    int sh = (nn == 16) ? 4 : 2;
    for (int sw = 0; sw < nsw; sw++) {
        for (int rnd = 0; rnd < rounds; rnd++) {
            if (lane < np) {
                int m_ = lane;
                int pp = (m_ == 0) ? 0 : ((m_ - 1 + rnd) % (nn - 1)) + 1;
                int i2 = nn - 1 - m_;
                int qq = ((i2 - 1 + rnd) % (nn - 1)) + 1;
                float app = G[pp * nn + pp], aqq = G[qq * nn + qq], apq = G[pp * nn + qq];
                float c = 1.f, sn = 0.f;
                if (fabsf(apq) > 1e-36f) {
                    float ta = (aqq - app) / (2.f * apq);
                    float t = ((ta >= 0.f) ? 1.f : -1.f) / (fabsf(ta) + sqrtf(1.f + ta * ta));
                    c = rsqrtf(1.f + t * t); sn = t * c;
                }
                s->csC[m_] = c; s->csS[m_] = sn; s->prI[m_] = pp; s->prJ[m_] = qq;
            }
            __syncwarp();
            int tot = nn * np;
            for (int e = lane; e < tot; e += 32) {
                int pr = e >> sh, row = e & (nn - 1);
                int pp = s->prI[pr], qq = s->prJ[pr];
                float c = s->csC[pr], sn = s->csS[pr];
                float gp = G[row * nn + pp], gq = G[row * nn + qq];
                G[row * nn + pp] = c * gp - sn * gq;
                G[row * nn + qq] = sn * gp + c * gq;
                float up = U[row * nn + pp], uq = U[row * nn + qq];
                U[row * nn + pp] = c * up - sn * uq;
                U[row * nn + qq] = sn * up + c * uq;
            }
            __syncwarp();
            for (int e = lane; e < tot; e += 32) {
                int pr = e >> sh, col = e & (nn - 1);
                int pp = s->prI[pr], qq = s->prJ[pr];
                float c = s->csC[pr], sn = s->csS[pr];
                float rp = G[pp * nn + col], rq = G[qq * nn + col];
                G[pp * nn + col] = c * rp - sn * rq;
                G[qq * nn + col] = sn * rp + c * rq;
            }
            __syncwarp();
        }
    }
}

// Left-to-right chi=4 truncation sweep + normalization, writes small[].
__device__ void leftSweep(SM* s, int lane) {
    float* m = s->scratch;
    float* G = s->scratch + 256;
    float* U = s->scratch + 512;
    int kprev = 0;
    for (int j = 0; j < 9; j++) {
        int r = s->R[j];
        int lT = s->L[j];
        int lb = (j == 0) ? s->L[0] : kprev;
        int nn = lb * 4;
        // m[(a*4+d)][rr]
        for (int e = lane; e < nn * r; e += 32) {
            int row = e / r, rr = e % r;
            int a = row >> 2, d4 = row & 3;
            float acc = 0.f;
            const float* M = s->mps + mpsOff(j);
            if (j == 0) acc = M[rr * 4 + d4];
            else {
                for (int bb = 0; bb < lT; bb++)
                    acc += s->sv[a * 16 + bb] * M[(bb * r + rr) * 4 + d4];
            }
            m[e] = acc;
        }
        __syncwarp();
        // G = m m^T; U = I
        for (int e = lane; e < nn * nn; e += 32) {
            int i1 = e / nn, i2 = e % nn;
            float acc = 0.f;
            for (int rr = 0; rr < r; rr++) acc += m[i1 * r + rr] * m[i2 * r + rr];
            G[e] = acc;
            U[e] = (i1 == i2) ? 1.f : 0.f;
        }
        __syncwarp();
        jacobi(s, lane, nn);
        int k = 4; if (nn < k) k = nn; if (r < k) k = r;
        if (lane == 0) {
            float dv[16];
            for (int t = 0; t < nn; t++) dv[t] = G[t * nn + t];
            for (int b2 = 0; b2 < k; b2++) {
                int bi = 0; float bv = -1e38f;
                for (int t = 0; t < nn; t++) if (dv[t] > bv) { bv = dv[t]; bi = t; }
                s->kidx[b2] = bi; dv[bi] = -1e38f;
            }
        }
        __syncwarp();
        // svt = U_k^T m  (k x r), stride 16
        for (int e = lane; e < k * r; e += 32) {
            int b2 = e / r, rr = e % r;
            float acc = 0.f;
            int ci = s->kidx[b2];
            for (int row = 0; row < nn; row++) acc += U[row * nn + ci] * m[row * r + rr];
            s->sv[b2 * 16 + rr] = acc;
        }
        // small[j] = (lb, k, 4)
        for (int e = lane; e < lb * k * 4; e += 32) {
            int d4 = e & 3; int rest = e >> 2;
            int b2 = rest % k; int a = rest / k;
            s->small[j * 64 + e] = U[(a * 4 + d4) * nn + s->kidx[b2]];
        }
        if (lane == 0) { s->sL[j] = lb; s->sR[j] = k; }
        kprev = k;
        __syncwarp();
    }
    // site 9: absorb final svt
    {
        int R9 = s->R[9], L9 = s->L[9];
        const float* M = s->mps + mpsOff(9);
        int tot = kprev * R9 * 4;
        for (int e = lane; e < tot; e += 32) {
            int d4 = e & 3; int rest = e >> 2;
            int rr = rest % R9; int a = rest / R9;
            float acc = 0.f;
            for (int bb = 0; bb < L9; bb++)
                acc += s->sv[a * 16 + bb] * M[(bb * R9 + rr) * 4 + d4];
            s->small[9 * 64 + e] = acc;
        }
        if (lane == 0) { s->sL[9] = kprev; s->sR[9] = R9; }
        __syncwarp();
    }
    // normalize tensors, accumulate logn
    float lacc = 0.f;
    for (int j = 0; j < NSITE; j++) {
        int n = s->sL[j] * s->sR[j] * 4;
        float ss = 0.f;
        for (int e = lane; e < n; e += 32) { float t = s->small[j * 64 + e]; ss += t * t; }
        ss = wsum(ss);
        float nrm = sqrtf(ss);
        float inv = 1.f / nrm;
        for (int e = lane; e < n; e += 32) s->small[j * 64 + e] *= inv;
        lacc += logf(nrm);
    }
    if (lane == 0) s->logn += lacc;
    __syncwarp();
}

extern __shared__ float smraw[];

__global__ void __launch_bounds__(32)
amp_kernel(const int* __restrict__ x, const float* __restrict__ peps, float* __restrict__ out) {
    SM* s = (SM*)smraw;
    int lane = threadIdx.x;
    int b = blockIdx.x;
    for (int e = lane; e < 100; e += 32) s->xr[e] = x[b * 100 + e];
    if (lane == 0) s->logn = 0.f;
    __syncwarp();

    // bottom half: row 0, absorb rows 1..4
    initRow(s, peps, 0, lane, false);
    for (int i = 1; i <= 4; i++) {
        absorbRow(s, peps, i, lane, false);
        rightSweep(s, lane);
        leftSweep(s, lane);
    }
    for (int e = lane; e < 640; e += 32) s->botS[e] = s->small[e];
    if (lane < 10) { s->bL[lane] = s->sL[lane]; s->bR[lane] = s->sR[lane]; }
    __syncwarp();

    // top half: row 9, absorb rows 8..5
    initRow(s, peps, 9, lane, true);
    for (int i = 8; i >= 5; i--) {
        absorbRow(s, peps, i, lane, true);
        rightSweep(s, lane);
        leftSweep(s, lane);
    }

    // final zip: E(a,b) -> sum_{a,b,d} E * bot[a,c,d] * top[b,e,d]
    if (lane == 0) s->Ebuf[0] = 1.f;
    int eB = 1;
    __syncwarp();
    for (int j = 0; j < NSITE; j++) {
        int cdim = s->bR[j], edim = s->sR[j];
        int adim = s->bL[j], bdim = s->sL[j];
        if (lane < 16) {
            int c = lane >> 2, e2 = lane & 3;
            if (c < cdim && e2 < edim) {
                float acc = 0.f;
                for (int a = 0; a < adim; a++)
                    for (int bb = 0; bb < bdim; bb++) {
                        float ev = s->Ebuf[a * eB + bb];
                        float dot = 0.f;
                        #pragma unroll
                        for (int d4 = 0; d4 < 4; d4++)
                            dot += s->botS[j * 64 + (a * cdim + c) * 4 + d4]
                                 * s->small[j * 64 + (bb * edim + e2) * 4 + d4];
                        acc += ev * dot;
                    }
                s->Ebuf2[c * edim + e2] = acc;
            }
        }
        __syncwarp();
        if (lane < 16) s->Ebuf[lane] = s->Ebuf2[lane];
        eB = edim;
        __syncwarp();
    }
    if (lane == 0) out[b] = s->Ebuf[0] * expf(s->logn);
}

extern "C" void kernel_launch(void* const* d_in, const int* in_sizes, int n_in,
                              void* d_out, int out_size) {
    const int* x;
    const float* peps;
    // expected order: x (int32, 4096*100), peps (float32, 51200)
    if (in_sizes[0] == 51200 && n_in >= 2) {
        peps = (const float*)d_in[0];
        x = (const int*)d_in[1];
    } else {
        x = (const int*)d_in[0];
        peps = (const float*)d_in[1];
    }
    float* out = (float*)d_out;
    int nB = out_size;
    cudaFuncSetAttribute(amp_kernel, cudaFuncAttributeMaxDynamicSharedMemorySize, (int)sizeof(SM));
    amp_kernel<<<nB, 32, sizeof(SM)>>>(x, peps, out);
}

// round 3
// speedup vs baseline: 2.2926x; 2.2926x over previous
#include <cuda_runtime.h>
#include <math.h>

// Static dims: sites 0..9. small[j]: j0 (1,4,4)=16, j1-8 (4,4,4)=64, j9 (4,1,4)=16.
// Raw absorbed M: j0 (1,16,4)=256 (stored [(r)*4+d]), middle (16,16,4)=1024
// ([(l*16+r)*4+d]), j9 (16,1,4)=64 ([l*4+d]).
// F[j] = right environment of raw sites j+1..9 on bond r_j (16x16), j=0..8.

struct SM {
    float F[2304];      // 9 x 256
    float M[1024];
    float T[1024];      // env temp / W reuse
    float tb[256];      // staged peps site slice, linear (v,w,il,ic)
    float m[256];
    float G[256];
    float U[256];
    float sv[64];       // carry (4 x 16)
    float small[640];
    float botS[640];
    float Eb[16], Eb2[16];
    float csC[8], csS[8];
    float logn;
    int   prI[8], prJ[8];
    int   kidx[4];
    int   xr[100];
};

__device__ __forceinline__ float wsum(float v) {
    #pragma unroll
    for (int o = 16; o > 0; o >>= 1) v += __shfl_xor_sync(0xffffffffu, v, o);
    return v;
}

__device__ __forceinline__ void stage(SM* s, const float* __restrict__ peps, int i, int j, int lane) {
    const float* base = peps + (size_t)(i * 10 + j) * 512;
    int xp = s->xr[i * 10 + j];
    #pragma unroll
    for (int t = 0; t < 8; t++) s->tb[lane + 32 * t] = base[(lane + 32 * t) * 2 + xp];
}

// tb index: bottom sums over v with phys=w=ph; top sums over w with phys=v=ph.
template<bool TOP>
__device__ __forceinline__ float tslice(SM* s, int v, int ph, int il, int ic) {
    int idx = TOP ? (((ph * 4 + v) * 4 + il) * 4 + ic)
                  : (((v * 4 + ph) * 4 + il) * 4 + ic);
    return s->tb[idx];
}

template<bool TOP>
__device__ void absorbM(SM* s, int j, int lane) {
    const float* sm = s->small + j * 64;
    for (int t = 0; t < 32; t++) {
        int e = lane + 32 * t;
        int ph = e & 3, r = (e >> 2) & 15, l = e >> 6;
        int a = l >> 2, il = l & 3, b = r >> 2, ic = r & 3;
        const float* mr = sm + (a * 4 + b) * 4;
        float acc = 0.f;
        #pragma unroll
        for (int v = 0; v < 4; v++) acc += mr[v] * tslice<TOP>(s, v, ph, il, ic);
        s->M[e] = acc;
    }
}

template<bool TOP>
__device__ void absorb0(SM* s, int lane) {
    const float* sm = s->small;  // (b*4+v)
    #pragma unroll
    for (int t = 0; t < 8; t++) {
        int e = lane + 32 * t;
        int ph = e & 3, r = e >> 2;
        int b = r >> 2, ic = r & 3;
        const float* mr = sm + b * 4;
        float acc = 0.f;
        #pragma unroll
        for (int v = 0; v < 4; v++) acc += mr[v] * tslice<TOP>(s, v, ph, 0, ic);
        s->M[e] = acc;  // [(r)*4+ph]
    }
}

template<bool TOP>
__device__ void absorb9(SM* s, int lane) {
    const float* sm = s->small + 9 * 64;  // (a*4+v)
    #pragma unroll
    for (int t = 0; t < 2; t++) {
        int e = lane + 32 * t;
        int ph = e & 3, l = e >> 2;
        int a = l >> 2, il = l & 3;
        const float* mr = sm + a * 4;
        float acc = 0.f;
        #pragma unroll
        for (int v = 0; v < 4; v++) acc += mr[v] * tslice<TOP>(s, v, ph, il, 0);
        s->M[e] = acc;  // [l*4+ph]
    }
}

// F[j-1] = sum_d M_j F[j] M_j^T, middle sites.
__device__ void envM(SM* s, int j, int lane) {
    const float* Fj = s->F + j * 256;
    int l = lane >> 1, dh = (lane & 1) * 2;
    float Mr0[16], Mr1[16];
    const float* Mrow = s->M + l * 64 + dh;
    #pragma unroll
    for (int r2 = 0; r2 < 16; r2++) { Mr0[r2] = Mrow[r2 * 4]; Mr1[r2] = Mrow[r2 * 4 + 1]; }
    #pragma unroll 4
    for (int r = 0; r < 16; r++) {
        float a0 = 0.f, a1 = 0.f;
        #pragma unroll
        for (int r2 = 0; r2 < 16; r2++) {
            float f = Fj[r2 * 16 + r];
            a0 += Mr0[r2] * f; a1 += Mr1[r2] * f;
        }
        s->T[l * 64 + r * 4 + dh] = a0;
        s->T[l * 64 + r * 4 + dh + 1] = a1;
    }
    __syncwarp();
    float* Fn = s->F + (j - 1) * 256;
    for (int t = 0; t < 8; t++) {
        int e = lane + 32 * t;
        int l1 = e >> 4, l2 = e & 15;
        const float4* Tp = (const float4*)(s->T + l1 * 64);
        const float4* Mp = (const float4*)(s->M + l2 * 64);
        float acc = 0.f;
        #pragma unroll
        for (int q = 0; q < 16; q++) {
            float4 tv = Tp[q], mv = Mp[q];
            acc += tv.x * mv.x + tv.y * mv.y + tv.z * mv.z + tv.w * mv.w;
        }
        Fn[e] = acc;
    }
    __syncwarp();
}

// Cyclic Jacobi eigensolver on G (16x16 sym, in smem), accumulating U.
__device__ void jacobi16(SM* s, int lane) {
    for (int sw = 0; sw < 7; sw++)
    for (int rnd = 0; rnd < 15; rnd++) {
        if (lane < 8) {
            int pp = (lane == 0) ? 0 : ((lane - 1 + rnd) % 15) + 1;
            int qq = ((14 - lane + rnd) % 15) + 1;
            float app = s->G[pp * 16 + pp], aqq = s->G[qq * 16 + qq], apq = s->G[pp * 16 + qq];
            float c = 1.f, sn = 0.f;
            if (fabsf(apq) > 1e-36f) {
                float ta = (aqq - app) / (2.f * apq);
                float tt = ((ta >= 0.f) ? 1.f : -1.f) / (fabsf(ta) + sqrtf(1.f + ta * ta));
                c = rsqrtf(1.f + tt * tt); sn = tt * c;
            }
            s->csC[lane] = c; s->csS[lane] = sn; s->prI[lane] = pp; s->prJ[lane] = qq;
        }
        __syncwarp();
        #pragma unroll
        for (int t = 0; t < 4; t++) {
            int e = lane + 32 * t; int pr = e >> 4, row = e & 15;
            int pp = s->prI[pr], qq = s->prJ[pr];
            float c = s->csC[pr], sn = s->csS[pr];
            float gp = s->G[row * 16 + pp], gq = s->G[row * 16 + qq];
            s->G[row * 16 + pp] = c * gp - sn * gq;
            s->G[row * 16 + qq] = sn * gp + c * gq;
            float up = s->U[row * 16 + pp], uq = s->U[row * 16 + qq];
            s->U[row * 16 + pp] = c * up - sn * uq;
            s->U[row * 16 + qq] = sn * up + c * uq;
        }
        __syncwarp();
        #pragma unroll
        for (int t = 0; t < 4; t++) {
            int e = lane + 32 * t; int pr = e >> 4, col = e & 15;
            int pp = s->prI[pr], qq = s->prJ[pr];
            float c = s->csC[pr], sn = s->csS[pr];
            float rp = s->G[pp * 16 + col], rq = s->G[qq * 16 + col];
            s->G[pp * 16 + col] = c * rp - sn * rq;
            s->G[qq * 16 + col] = sn * rp + c * rq;
        }
        __syncwarp();
    }
}

template<bool TOP>
__device__ void initRow(SM* s, const float* __restrict__ peps, int i, int lane) {
    for (int j = 0; j < 10; j++) {
        stage(s, peps, i, j, lane);
        __syncwarp();
        if (j == 9) {
            if (lane < 16) {
                int ph = lane & 3, il = lane >> 2;
                s->small[9 * 64 + lane] = tslice<TOP>(s, 0, ph, il, 0);
            }
        } else {
            int n = (j == 0) ? 16 : 64;
            for (int e = lane; e < n; e += 32) {
                int ph = e & 3, ic = (e >> 2) & 3, il = e >> 4;
                s->small[j * 64 + e] = tslice<TOP>(s, 0, ph, il, ic);
            }
        }
        __syncwarp();
    }
}

template<bool TOP>
__device__ void compress(SM* s, const float* __restrict__ peps, int i, int lane) {
    // ---- Phase A: right environments ----
    stage(s, peps, i, 9, lane); __syncwarp();
    absorb9<TOP>(s, lane); __syncwarp();
    #pragma unroll
    for (int t = 0; t < 8; t++) {
        int e = lane + 32 * t; int l = e >> 4, l2 = e & 15;
        float acc = 0.f;
        #pragma unroll
        for (int d = 0; d < 4; d++) acc += s->M[l * 4 + d] * s->M[l2 * 4 + d];
        s->F[8 * 256 + e] = acc;
    }
    __syncwarp();
    for (int j = 8; j >= 2; j--) {
        stage(s, peps, i, j, lane); __syncwarp();
        absorbM<TOP>(s, j, lane); __syncwarp();
        envM(s, j, lane);
    }
    // ---- Phase B: left sweep ----
    stage(s, peps, i, 0, lane); __syncwarp();
    absorb0<TOP>(s, lane); __syncwarp();
    // site 0: k = nn = 4 -> keep-all; U = I is a valid gauge choice.
    if (lane < 16) {
        int b = lane >> 2, d = lane & 3;
        s->small[b * 4 + d] = (b == d) ? 1.f : 0.f;
    }
    #pragma unroll
    for (int t = 0; t < 2; t++) {
        int e = lane + 32 * t; int r = e & 15, dd = e >> 4;
        s->sv[dd * 16 + r] = s->M[r * 4 + dd];
    }
    __syncwarp();
    for (int j = 1; j <= 8; j++) {
        stage(s, peps, i, j, lane); __syncwarp();
        absorbM<TOP>(s, j, lane); __syncwarp();
        // m[(a*4+d), r] = sum_b sv[a,b] M[b, r, d]
        for (int t = 0; t < 8; t++) {
            int e = lane + 32 * t; int r = e & 15, row = e >> 4;
            int a = row >> 2, d = row & 3;
            float acc = 0.f;
            #pragma unroll
            for (int b = 0; b < 16; b++) acc += s->sv[a * 16 + b] * s->M[b * 64 + r * 4 + d];
            s->m[e] = acc;
        }
        __syncwarp();
        // W = m * F[j]  (into T)
        const float* Fj = s->F + j * 256;
        for (int t = 0; t < 8; t++) {
            int e = lane + 32 * t; int r = e & 15, row = e >> 4;
            float acc = 0.f;
            #pragma unroll
            for (int r2 = 0; r2 < 16; r2++) acc += s->m[row * 16 + r2] * Fj[r2 * 16 + r];
            s->T[e] = acc;
        }
        __syncwarp();
        // G = W * m^T ; U = I
        for (int t = 0; t < 8; t++) {
            int e = lane + 32 * t; int row2 = e & 15, row = e >> 4;
            const float4* Wp = (const float4*)(s->T + row * 16);
            const float4* mp = (const float4*)(s->m + row2 * 16);
            float acc = 0.f;
            #pragma unroll
            for (int q = 0; q < 4; q++) {
                float4 wv = Wp[q], mv = mp[q];
                acc += wv.x * mv.x + wv.y * mv.y + wv.z * mv.z + wv.w * mv.w;
            }
            s->G[e] = acc;
            s->U[e] = (row == row2) ? 1.f : 0.f;
        }
        __syncwarp();
        jacobi16(s, lane);
        if (lane == 0) {
            float dv[16];
            #pragma unroll
            for (int q = 0; q < 16; q++) dv[q] = s->G[q * 16 + q];
            #pragma unroll
            for (int b = 0; b < 4; b++) {
                int bi = 0; float bv = dv[0];
                #pragma unroll
                for (int q = 1; q < 16; q++) if (dv[q] > bv) { bv = dv[q]; bi = q; }
                s->kidx[b] = bi; dv[bi] = -3e38f;
            }
        }
        __syncwarp();
        // small[j][(a*4+b)*4+d] = U[(a*4+d), kidx[b]]
        #pragma unroll
        for (int t = 0; t < 2; t++) {
            int e = lane + 32 * t;
            int d = e & 3, b = (e >> 2) & 3, a = e >> 4;
            s->small[j * 64 + e] = s->U[(a * 4 + d) * 16 + s->kidx[b]];
        }
        // sv[b, r] = sum_row U[row, kidx[b]] m[row, r]
        #pragma unroll
        for (int t = 0; t < 2; t++) {
            int e = lane + 32 * t; int r = e & 15, b = e >> 4;
            int ci = s->kidx[b];
            float acc = 0.f;
            #pragma unroll
            for (int row = 0; row < 16; row++) acc += s->U[row * 16 + ci] * s->m[row * 16 + r];
            s->sv[e] = acc;
        }
        __syncwarp();
    }
    // site 9: small[9] = sv * M9
    stage(s, peps, i, 9, lane); __syncwarp();
    absorb9<TOP>(s, lane); __syncwarp();
    if (lane < 16) {
        int d = lane & 3, a = lane >> 2;
        float acc = 0.f;
        #pragma unroll
        for (int b = 0; b < 16; b++) acc += s->sv[a * 16 + b] * s->M[b * 4 + d];
        s->small[9 * 64 + lane] = acc;
    }
    __syncwarp();
    // ---- Phase C: normalize + logn ----
    float lacc = 0.f;
    for (int js = 0; js < 10; js++) {
        int n = (js == 0 || js == 9) ? 16 : 64;
        float ss = 0.f;
        for (int e = lane; e < n; e += 32) { float v = s->small[js * 64 + e]; ss += v * v; }
        ss = wsum(ss);
        float nrm = sqrtf(ss), inv = 1.f / nrm;
        for (int e = lane; e < n; e += 32) s->small[js * 64 + e] *= inv;
        lacc += logf(nrm);
    }
    if (lane == 0) s->logn += lacc;
    __syncwarp();
}

extern __shared__ float smraw[];

__global__ void __launch_bounds__(32)
amp_kernel(const int* __restrict__ x, const float* __restrict__ peps, float* __restrict__ out) {
    SM* s = (SM*)smraw;
    int lane = threadIdx.x;
    int blk = blockIdx.x;
    for (int e = lane; e < 100; e += 32) s->xr[e] = x[blk * 100 + e];
    if (lane == 0) s->logn = 0.f;
    __syncwarp();

    initRow<false>(s, peps, 0, lane);
    for (int i = 1; i <= 4; i++) compress<false>(s, peps, i, lane);
    #pragma unroll
    for (int t = 0; t < 20; t++) s->botS[lane + 32 * t] = s->small[lane + 32 * t];
    __syncwarp();

    initRow<true>(s, peps, 9, lane);
    for (int i = 8; i >= 5; i--) compress<true>(s, peps, i, lane);

    // ---- zip ----
    // j=0: bot (1,4,4), top (1,4,4)
    if (lane < 16) {
        int c = lane >> 2, e2 = lane & 3;
        float acc = 0.f;
        #pragma unroll
        for (int d = 0; d < 4; d++) acc += s->botS[c * 4 + d] * s->small[e2 * 4 + d];
        s->Eb[lane] = acc;
    }
    __syncwarp();
    for (int j = 1; j <= 8; j++) {
        if (lane < 16) {
            int c = lane >> 2, e2 = lane & 3;
            float acc = 0.f;
            #pragma unroll
            for (int a = 0; a < 4; a++)
                #pragma unroll
                for (int b = 0; b < 4; b++) {
                    float ev = s->Eb[a * 4 + b];
                    float dot = 0.f;
                    #pragma unroll
                    for (int d = 0; d < 4; d++)
                        dot += s->botS[j * 64 + (a * 4 + c) * 4 + d]
                             * s->small[j * 64 + (b * 4 + e2) * 4 + d];
                    acc += ev * dot;
                }
            s->Eb2[lane] = acc;
        }
        __syncwarp();
        if (lane < 16) s->Eb[lane] = s->Eb2[lane];
        __syncwarp();
    }
    float part = 0.f;
    if (lane < 16) {
        int a = lane >> 2, b = lane & 3;
        float dot = 0.f;
        #pragma unroll
        for (int d = 0; d < 4; d++)
            dot += s->botS[9 * 64 + a * 4 + d] * s->small[9 * 64 + b * 4 + d];
        part = s->Eb[a * 4 + b] * dot;
    }
    part = wsum(part);
    if (lane == 0) out[blk] = part * expf(s->logn);
}

extern "C" void kernel_launch(void* const* d_in, const int* in_sizes, int n_in,
                              void* d_out, int out_size) {
    const int* x;
    const float* peps;
    if (in_sizes[0] == 51200 && n_in >= 2) {
        peps = (const float*)d_in[0];
        x = (const int*)d_in[1];
    } else {
        x = (const int*)d_in[0];
        peps = (const float*)d_in[1];
    }
    float* out = (float*)d_out;
    cudaFuncSetAttribute(amp_kernel, cudaFuncAttributeMaxDynamicSharedMemorySize, (int)sizeof(SM));
    amp_kernel<<<out_size, 32, sizeof(SM)>>>(x, peps, out);
}

// round 4
// speedup vs baseline: 10.5996x; 4.6235x over previous
#include <cuda_runtime.h>
#include <math.h>

// Static dims: small[j]: j0 (1,4,4)=16, j1-8 (4,4,4)=64, j9 (4,1,4)=16.
// Middle raw M: (16,16,4) stored [l*68 + r*4 + d] (stride-68 rows, conflict-free).
// j0 M: [r*4+d] flat 64.  j9 M: [l*4+d] flat 64.
// F[j] = right env of raw sites j+1..9 (16x16, row stride 16), j=1..8 used.
// G,U: 16x16 with row stride 17 (conflict-free col access).
// m: 16x16 with row stride 20 (conflict-free float4 rows).

struct SM {
    float F[2304];
    float M[1088];
    float T[1088];      // envM temp (stride 68) / W (16x16 flat, stride 16) in left sweep
    float tb[256];
    float m[320];
    float G[272];
    float U[272];
    float sv[64];
    float small[640];
    float botS[640];
    float Eb[16], Eb2[16];
    float logn;
    int   kidx[4];
    int   xr[100];
};

__device__ __forceinline__ float wsum(float v) {
    #pragma unroll
    for (int o = 16; o > 0; o >>= 1) v += __shfl_xor_sync(0xffffffffu, v, o);
    return v;
}

__device__ __forceinline__ void stage(SM* s, const float* __restrict__ peps, int i, int j, int lane) {
    const float* base = peps + (size_t)(i * 10 + j) * 512;
    int xp = s->xr[i * 10 + j];
    #pragma unroll
    for (int t = 0; t < 8; t++) s->tb[lane + 32 * t] = base[(lane + 32 * t) * 2 + xp];
}

template<bool TOP>
__device__ __forceinline__ float tslice(SM* s, int v, int ph, int il, int ic) {
    int idx = TOP ? (((ph * 4 + v) * 4 + il) * 4 + ic)
                  : (((v * 4 + ph) * 4 + il) * 4 + ic);
    return s->tb[idx];
}

template<bool TOP>
__device__ void absorbM(SM* s, int j, int lane) {
    const float* sm = s->small + j * 64;
    #pragma unroll 4
    for (int t = 0; t < 32; t++) {
        int e = lane + 32 * t;
        int ph = e & 3, r = (e >> 2) & 15, l = e >> 6;
        int a = l >> 2, il = l & 3, b = r >> 2, ic = r & 3;
        const float* mr = sm + (a * 4 + b) * 4;
        float acc = 0.f;
        #pragma unroll
        for (int v = 0; v < 4; v++) acc += mr[v] * tslice<TOP>(s, v, ph, il, ic);
        s->M[l * 68 + r * 4 + ph] = acc;
    }
}

template<bool TOP>
__device__ void absorb0(SM* s, int lane) {
    const float* sm = s->small;
    #pragma unroll
    for (int t = 0; t < 2; t++) {
        int e = lane + 32 * t;
        int ph = e & 3, r = e >> 2;
        int b = r >> 2, ic = r & 3;
        const float* mr = sm + b * 4;
        float acc = 0.f;
        #pragma unroll
        for (int v = 0; v < 4; v++) acc += mr[v] * tslice<TOP>(s, v, ph, 0, ic);
        s->M[e] = acc;  // [r*4+ph]
    }
}

template<bool TOP>
__device__ void absorb9(SM* s, int lane) {
    const float* sm = s->small + 9 * 64;
    #pragma unroll
    for (int t = 0; t < 2; t++) {
        int e = lane + 32 * t;
        int ph = e & 3, l = e >> 2;
        int a = l >> 2, il = l & 3;
        const float* mr = sm + a * 4;
        float acc = 0.f;
        #pragma unroll
        for (int v = 0; v < 4; v++) acc += mr[v] * tslice<TOP>(s, v, ph, il, 0);
        s->M[e] = acc;  // [l*4+ph]
    }
}

// F[j-1] = sum_d M_j F[j] M_j^T (middle sites, M stride 68).
__device__ void envM(SM* s, int j, int lane) {
    const float* Fj = s->F + j * 256;
    // T[l*68 + r*4 + d] = sum_r2 M[l*68 + r2*4 + d] * Fj[r2*16 + r]
    #pragma unroll
    for (int g = 0; g < 2; g++) {
        int idx = lane + 32 * g;          // idx = 4*l + d
        int l = idx >> 2, d = idx & 3;
        float Mr[16];
        #pragma unroll
        for (int r2 = 0; r2 < 16; r2++) Mr[r2] = s->M[l * 68 + r2 * 4 + d];
        #pragma unroll 4
        for (int r = 0; r < 16; r++) {
            float acc = 0.f;
            #pragma unroll
            for (int r2 = 0; r2 < 16; r2++) acc += Mr[r2] * Fj[r2 * 16 + r];
            s->T[l * 68 + r * 4 + d] = acc;
        }
    }
    __syncwarp();
    float* Fn = s->F + (j - 1) * 256;
    #pragma unroll
    for (int t = 0; t < 8; t++) {
        int e = lane + 32 * t;
        int l1 = e >> 4, l2 = e & 15;
        const float4* Tp = (const float4*)(s->T + l1 * 68);
        const float4* Mp = (const float4*)(s->M + l2 * 68);
        float acc = 0.f;
        #pragma unroll
        for (int q = 0; q < 16; q++) {
            float4 tv = Tp[q], mv = Mp[q];
            acc += tv.x * mv.x + tv.y * mv.y + tv.z * mv.z + tv.w * mv.w;
        }
        Fn[e] = acc;
    }
    __syncwarp();
}

__device__ __forceinline__ int pairP(int pr, int rnd) {
    return (pr == 0) ? 0 : ((pr - 1 + rnd) % 15) + 1;
}
__device__ __forceinline__ int pairQ(int pr, int rnd) {
    return ((14 - pr + rnd) % 15) + 1;
}

// Cyclic Jacobi on G (16x16 sym, stride 17), accumulating U (stride 17).
__device__ void jacobi16(SM* s, int lane) {
    int row = lane & 15;
    int half = lane >> 4;
    for (int sw = 0; sw < 7; sw++) {
        if (sw >= 2) {
            float off = 0.f, dia = 0.f;
            #pragma unroll
            for (int t = 0; t < 8; t++) {
                int e = lane + 32 * t; int rw = e >> 4, cl = e & 15;
                float v = s->G[rw * 17 + cl];
                if (rw == cl) dia += v * v; else off += v * v;
            }
            off = wsum(off); dia = wsum(dia);
            if (off <= 1e-13f * dia) break;
        }
        for (int rnd = 0; rnd < 15; rnd++) {
            float creg = 1.f, sreg = 0.f;
            if (lane < 8) {
                int pp = pairP(lane, rnd), qq = pairQ(lane, rnd);
                float app = s->G[pp * 17 + pp], aqq = s->G[qq * 17 + qq], apq = s->G[pp * 17 + qq];
                if (fabsf(apq) > 1e-36f) {
                    float ta = (aqq - app) / (2.f * apq);
                    float tt = ((ta >= 0.f) ? 1.f : -1.f) / (fabsf(ta) + sqrtf(1.f + ta * ta));
                    creg = rsqrtf(1.f + tt * tt); sreg = tt * creg;
                }
            }
            // column rotations on G and U
            #pragma unroll
            for (int t = 0; t < 4; t++) {
                int pr = half + 2 * t;
                int pp = pairP(pr, rnd), qq = pairQ(pr, rnd);
                float c = __shfl_sync(0xffffffffu, creg, pr);
                float sn = __shfl_sync(0xffffffffu, sreg, pr);
                float gp = s->G[row * 17 + pp], gq = s->G[row * 17 + qq];
                s->G[row * 17 + pp] = c * gp - sn * gq;
                s->G[row * 17 + qq] = sn * gp + c * gq;
                float up = s->U[row * 17 + pp], uq = s->U[row * 17 + qq];
                s->U[row * 17 + pp] = c * up - sn * uq;
                s->U[row * 17 + qq] = sn * up + c * uq;
            }
            __syncwarp();
            // row rotations on G
            #pragma unroll
            for (int t = 0; t < 4; t++) {
                int pr = half + 2 * t;
                int pp = pairP(pr, rnd), qq = pairQ(pr, rnd);
                float c = __shfl_sync(0xffffffffu, creg, pr);
                float sn = __shfl_sync(0xffffffffu, sreg, pr);
                float rp = s->G[pp * 17 + row], rq = s->G[qq * 17 + row];
                s->G[pp * 17 + row] = c * rp - sn * rq;
                s->G[qq * 17 + row] = sn * rp + c * rq;
            }
            __syncwarp();
        }
    }
}

template<bool TOP>
__device__ void initRow(SM* s, const float* __restrict__ peps, int i, int lane) {
    for (int j = 0; j < 10; j++) {
        stage(s, peps, i, j, lane);
        __syncwarp();
        if (j == 9) {
            if (lane < 16) {
                int ph = lane & 3, il = lane >> 2;
                s->small[9 * 64 + lane] = tslice<TOP>(s, 0, ph, il, 0);
            }
        } else {
            int n = (j == 0) ? 16 : 64;
            for (int e = lane; e < n; e += 32) {
                int ph = e & 3, ic = (e >> 2) & 3, il = e >> 4;
                s->small[j * 64 + e] = tslice<TOP>(s, 0, ph, il, ic);
            }
        }
        __syncwarp();
    }
}

template<bool TOP>
__device__ void compress(SM* s, const float* __restrict__ peps, int i, int lane) {
    // ---- Phase A: right environments ----
    stage(s, peps, i, 9, lane); __syncwarp();
    absorb9<TOP>(s, lane); __syncwarp();
    #pragma unroll
    for (int t = 0; t < 8; t++) {
        int e = lane + 32 * t; int l = e >> 4, l2 = e & 15;
        float acc = 0.f;
        #pragma unroll
        for (int d = 0; d < 4; d++) acc += s->M[l * 4 + d] * s->M[l2 * 4 + d];
        s->F[8 * 256 + e] = acc;
    }
    __syncwarp();
    for (int j = 8; j >= 2; j--) {
        stage(s, peps, i, j, lane); __syncwarp();
        absorbM<TOP>(s, j, lane); __syncwarp();
        envM(s, j, lane);
    }
    // ---- Phase B: left sweep ----
    stage(s, peps, i, 0, lane); __syncwarp();
    absorb0<TOP>(s, lane); __syncwarp();
    // site 0: k = nn = 4, keep-all; U = I is a valid gauge.
    if (lane < 16) {
        int b = lane >> 2, d = lane & 3;
        s->small[b * 4 + d] = (b == d) ? 1.f : 0.f;
    }
    #pragma unroll
    for (int t = 0; t < 2; t++) {
        int e = lane + 32 * t; int r = e & 15, dd = e >> 4;
        s->sv[dd * 16 + r] = s->M[r * 4 + dd];
    }
    __syncwarp();
    for (int j = 1; j <= 8; j++) {
        stage(s, peps, i, j, lane); __syncwarp();
        absorbM<TOP>(s, j, lane); __syncwarp();
        // m[(a*4+d), r] = sum_b sv[a,b] M[b, r, d]
        #pragma unroll
        for (int t = 0; t < 8; t++) {
            int e = lane + 32 * t; int r = e & 15, rowp = e >> 4;
            int a = rowp >> 2, d = rowp & 3;
            float acc = 0.f;
            #pragma unroll
            for (int b = 0; b < 16; b++) acc += s->sv[a * 16 + b] * s->M[b * 68 + r * 4 + d];
            s->m[rowp * 20 + r] = acc;
        }
        __syncwarp();
        // W = m * F[j]  (stored in T, stride 16)
        const float* Fj = s->F + j * 256;
        #pragma unroll
        for (int t = 0; t < 8; t++) {
            int e = lane + 32 * t; int r = e & 15, rowp = e >> 4;
            float acc = 0.f;
            #pragma unroll
            for (int r2 = 0; r2 < 16; r2++) acc += s->m[rowp * 20 + r2] * Fj[r2 * 16 + r];
            s->T[rowp * 16 + r] = acc;
        }
        __syncwarp();
        // G = W * m^T ; U = I (stride-17 layouts)
        #pragma unroll
        for (int t = 0; t < 8; t++) {
            int e = lane + 32 * t; int row2 = e & 15, rowp = e >> 4;
            const float4* Wp = (const float4*)(s->T + rowp * 16);
            const float4* mp = (const float4*)(s->m + row2 * 20);
            float acc = 0.f;
            #pragma unroll
            for (int q = 0; q < 4; q++) {
                float4 wv = Wp[q], mv = mp[q];
                acc += wv.x * mv.x + wv.y * mv.y + wv.z * mv.z + wv.w * mv.w;
            }
            s->G[rowp * 17 + row2] = acc;
            s->U[rowp * 17 + row2] = (rowp == row2) ? 1.f : 0.f;
        }
        __syncwarp();
        jacobi16(s, lane);
        if (lane == 0) {
            float dv[16];
            #pragma unroll
            for (int q = 0; q < 16; q++) dv[q] = s->G[q * 17 + q];
            #pragma unroll
            for (int b = 0; b < 4; b++) {
                int bi = 0; float bv = dv[0];
                #pragma unroll
                for (int q = 1; q < 16; q++) if (dv[q] > bv) { bv = dv[q]; bi = q; }
                s->kidx[b] = bi; dv[bi] = -3e38f;
            }
        }
        __syncwarp();
        // small[j][(a*4+b)*4+d] = U[(a*4+d), kidx[b]]
        #pragma unroll
        for (int t = 0; t < 2; t++) {
            int e = lane + 32 * t;
            int d = e & 3, b = (e >> 2) & 3, a = e >> 4;
            s->small[j * 64 + e] = s->U[(a * 4 + d) * 17 + s->kidx[b]];
        }
        // sv[b, r] = sum_row U[row, kidx[b]] m[row, r]
        #pragma unroll
        for (int t = 0; t < 2; t++) {
            int e = lane + 32 * t; int r = e & 15, b = e >> 4;
            int ci = s->kidx[b];
            float acc = 0.f;
            #pragma unroll
            for (int rowp = 0; rowp < 16; rowp++) acc += s->U[rowp * 17 + ci] * s->m[rowp * 20 + r];
            s->sv[e] = acc;
        }
        __syncwarp();
    }
    // site 9
    stage(s, peps, i, 9, lane); __syncwarp();
    absorb9<TOP>(s, lane); __syncwarp();
    if (lane < 16) {
        int d = lane & 3, a = lane >> 2;
        float acc = 0.f;
        #pragma unroll
        for (int b = 0; b < 16; b++) acc += s->sv[a * 16 + b] * s->M[b * 4 + d];
        s->small[9 * 64 + lane] = acc;
    }
    __syncwarp();
    // ---- Phase C: normalize + logn ----
    float lacc = 0.f;
    for (int js = 0; js < 10; js++) {
        int n = (js == 0 || js == 9) ? 16 : 64;
        float ss = 0.f;
        for (int e = lane; e < n; e += 32) { float v = s->small[js * 64 + e]; ss += v * v; }
        ss = wsum(ss);
        float nrm = sqrtf(ss), inv = 1.f / nrm;
        for (int e = lane; e < n; e += 32) s->small[js * 64 + e] *= inv;
        lacc += logf(nrm);
    }
    if (lane == 0) s->logn += lacc;
    __syncwarp();
}

extern __shared__ float smraw[];

__global__ void __launch_bounds__(32)
amp_kernel(const int* __restrict__ x, const float* __restrict__ peps, float* __restrict__ out) {
    SM* s = (SM*)smraw;
    int lane = threadIdx.x;
    int blk = blockIdx.x;
    for (int e = lane; e < 100; e += 32) s->xr[e] = x[blk * 100 + e];
    if (lane == 0) s->logn = 0.f;
    __syncwarp();

    initRow<false>(s, peps, 0, lane);
    for (int i = 1; i <= 4; i++) compress<false>(s, peps, i, lane);
    #pragma unroll
    for (int t = 0; t < 20; t++) s->botS[lane + 32 * t] = s->small[lane + 32 * t];
    __syncwarp();

    initRow<true>(s, peps, 9, lane);
    for (int i = 8; i >= 5; i--) compress<true>(s, peps, i, lane);

    // ---- zip ----
    if (lane < 16) {
        int c = lane >> 2, e2 = lane & 3;
        float acc = 0.f;
        #pragma unroll
        for (int d = 0; d < 4; d++) acc += s->botS[c * 4 + d] * s->small[e2 * 4 + d];
        s->Eb[lane] = acc;
    }
    __syncwarp();
    for (int j = 1; j <= 8; j++) {
        if (lane < 16) {
            int c = lane >> 2, e2 = lane & 3;
            float acc = 0.f;
            #pragma unroll
            for (int a = 0; a < 4; a++)
                #pragma unroll
                for (int b = 0; b < 4; b++) {
                    float ev = s->Eb[a * 4 + b];
                    float dot = 0.f;
                    #pragma unroll
                    for (int d = 0; d < 4; d++)
                        dot += s->botS[j * 64 + (a * 4 + c) * 4 + d]
                             * s->small[j * 64 + (b * 4 + e2) * 4 + d];
                    acc += ev * dot;
                }
            s->Eb2[lane] = acc;
        }
        __syncwarp();
        if (lane < 16) s->Eb[lane] = s->Eb2[lane];
        __syncwarp();
    }
    float part = 0.f;
    if (lane < 16) {
        int a = lane >> 2, b = lane & 3;
        float dot = 0.f;
        #pragma unroll
        for (int d = 0; d < 4; d++)
            dot += s->botS[9 * 64 + a * 4 + d] * s->small[9 * 64 + b * 4 + d];
        part = s->Eb[a * 4 + b] * dot;
    }
    part = wsum(part);
    if (lane == 0) out[blk] = part * expf(s->logn);
}

extern "C" void kernel_launch(void* const* d_in, const int* in_sizes, int n_in,
                              void* d_out, int out_size) {
    const int* x;
    const float* peps;
    if (in_sizes[0] == 51200 && n_in >= 2) {
        peps = (const float*)d_in[0];
        x = (const int*)d_in[1];
    } else {
        x = (const int*)d_in[0];
        peps = (const float*)d_in[1];
    }
    float* out = (float*)d_out;
    cudaFuncSetAttribute(amp_kernel, cudaFuncAttributeMaxDynamicSharedMemorySize, (int)sizeof(SM));
    amp_kernel<<<out_size, 32, sizeof(SM)>>>(x, peps, out);
}

// round 7
// speedup vs baseline: 13.8176x; 1.3036x over previous
#include <cuda_runtime.h>
#include <math.h>

// Layouts (identical to the passing R3 kernel except G):
//  M: raw absorbed middle tensor (16,16,4): [l*68 + r*4 + d]  (stride-68 rows)
//  M site0: [r*4+d] (64); site9: [l*4+d] (64)
//  F: right envs, slot j holds env of bond j (16x16, stride 16), j=1..8
//  m: 16x16, row stride 20.
//  G: COLUMN-major, col stride 20 (G[col*20 + row]) — one-sided Jacobi target.
//  tb: staged peps site slice, linear (v,w,il,ic)

struct SM {
    float F[2304];
    float M[1088];
    float T[1088];      // envM temp (stride 68) / W (16x16, stride 16)
    float tb[256];
    float m[320];
    float G[320];
    float sv[64];
    float small[640];
    float botS[640];
    float Eb[16], Eb2[16];
    float cn[16];
    float invn[4];
    float logn;
    int   kidx[4];
    int   xr[100];
};

__device__ __forceinline__ float wsum(float v) {
    #pragma unroll
    for (int o = 16; o > 0; o >>= 1) v += __shfl_xor_sync(0xffffffffu, v, o);
    return v;
}

__device__ __forceinline__ void stage(SM* s, const float* __restrict__ peps, int i, int j, int lane) {
    const float* base = peps + (size_t)(i * 10 + j) * 512;
    int xp = s->xr[i * 10 + j];
    #pragma unroll
    for (int t = 0; t < 8; t++) s->tb[lane + 32 * t] = base[(lane + 32 * t) * 2 + xp];
}

template<bool TOP>
__device__ __forceinline__ float tslice(SM* s, int v, int ph, int il, int ic) {
    int idx = TOP ? (((ph * 4 + v) * 4 + il) * 4 + ic)
                  : (((v * 4 + ph) * 4 + il) * 4 + ic);
    return s->tb[idx];
}

template<bool TOP>
__device__ void absorbM(SM* s, int j, int lane) {
    const float* sm = s->small + j * 64;
    #pragma unroll 4
    for (int t = 0; t < 32; t++) {
        int e = lane + 32 * t;
        int ph = e & 3, r = (e >> 2) & 15, l = e >> 6;
        int a = l >> 2, il = l & 3, b = r >> 2, ic = r & 3;
        const float* mr = sm + (a * 4 + b) * 4;
        float acc = 0.f;
        #pragma unroll
        for (int v = 0; v < 4; v++) acc += mr[v] * tslice<TOP>(s, v, ph, il, ic);
        s->M[l * 68 + r * 4 + ph] = acc;
    }
}

template<bool TOP>
__device__ void absorb0(SM* s, int lane) {
    const float* sm = s->small;
    #pragma unroll
    for (int t = 0; t < 2; t++) {
        int e = lane + 32 * t;
        int ph = e & 3, r = e >> 2;
        int b = r >> 2, ic = r & 3;
        const float* mr = sm + b * 4;
        float acc = 0.f;
        #pragma unroll
        for (int v = 0; v < 4; v++) acc += mr[v] * tslice<TOP>(s, v, ph, 0, ic);
        s->M[e] = acc;  // [r*4+ph]
    }
}

template<bool TOP>
__device__ void absorb9(SM* s, int lane) {
    const float* sm = s->small + 9 * 64;
    #pragma unroll
    for (int t = 0; t < 2; t++) {
        int e = lane + 32 * t;
        int ph = e & 3, l = e >> 2;
        int a = l >> 2, il = l & 3;
        const float* mr = sm + a * 4;
        float acc = 0.f;
        #pragma unroll
        for (int v = 0; v < 4; v++) acc += mr[v] * tslice<TOP>(s, v, ph, il, 0);
        s->M[e] = acc;  // [l*4+ph]
    }
}

// F[j-1] = sum_d M_j F[j] M_j^T (middle sites, M stride 68).
__device__ void envM(SM* s, int j, int lane) {
    const float* Fj = s->F + j * 256;
    #pragma unroll
    for (int g = 0; g < 2; g++) {
        int idx = lane + 32 * g;          // idx = 4*l + d
        int l = idx >> 2, d = idx & 3;
        float Mr[16];
        #pragma unroll
        for (int r2 = 0; r2 < 16; r2++) Mr[r2] = s->M[l * 68 + r2 * 4 + d];
        #pragma unroll 4
        for (int r = 0; r < 16; r++) {
            float acc = 0.f;
            #pragma unroll
            for (int r2 = 0; r2 < 16; r2++) acc += Mr[r2] * Fj[r2 * 16 + r];
            s->T[l * 68 + r * 4 + d] = acc;
        }
    }
    __syncwarp();
    float* Fn = s->F + (j - 1) * 256;
    #pragma unroll
    for (int t = 0; t < 8; t++) {
        int e = lane + 32 * t;
        int l1 = e >> 4, l2 = e & 15;
        const float4* Tp = (const float4*)(s->T + l1 * 68);
        const float4* Mp = (const float4*)(s->M + l2 * 68);
        float acc = 0.f;
        #pragma unroll
        for (int q = 0; q < 16; q++) {
            float4 tv = Tp[q], mv = Mp[q];
            acc += tv.x * mv.x + tv.y * mv.y + tv.z * mv.z + tv.w * mv.w;
        }
        Fn[e] = acc;
    }
    __syncwarp();
}

__device__ __forceinline__ int pairP(int pr, int rnd) {
    return (pr == 0) ? 0 : ((pr - 1 + rnd) % 15) + 1;
}
__device__ __forceinline__ int pairQ(int pr, int rnd) {
    return ((14 - pr + rnd) % 15) + 1;
}

// One-sided Jacobi on G (col-major, stride 20): columns -> lambda_i * u_i.
// Fixed 6 sweeps; rotations are exactly orthogonal so columns span is preserved.
__device__ void onesided16(SM* s, int lane) {
    int pr = lane >> 2, ql = lane & 3;
    float* Gc = s->G;
    for (int sw = 0; sw < 6; sw++) {
        for (int rnd = 0; rnd < 15; rnd++) {
            int p = pairP(pr, rnd), q = pairQ(pr, rnd);
            float4 gp = *(float4*)(Gc + p * 20 + ql * 4);
            float4 gq = *(float4*)(Gc + q * 20 + ql * 4);
            float dpp = gp.x * gp.x + gp.y * gp.y + gp.z * gp.z + gp.w * gp.w;
            float dqq = gq.x * gq.x + gq.y * gq.y + gq.z * gq.z + gq.w * gq.w;
            float dpq = gp.x * gq.x + gp.y * gq.y + gp.z * gq.z + gp.w * gq.w;
            dpp += __shfl_xor_sync(0xffffffffu, dpp, 1);
            dpp += __shfl_xor_sync(0xffffffffu, dpp, 2);
            dqq += __shfl_xor_sync(0xffffffffu, dqq, 1);
            dqq += __shfl_xor_sync(0xffffffffu, dqq, 2);
            dpq += __shfl_xor_sync(0xffffffffu, dpq, 1);
            dpq += __shfl_xor_sync(0xffffffffu, dpq, 2);
            float den = dpp * dqq;
            float r2 = dpq * dpq;
            float c = 1.f, sn = 0.f;
            if (r2 > 1e-30f * den && r2 > 0.f) {
                float ta = (dqq - dpp) / (2.f * dpq);
                float tt = ((ta >= 0.f) ? 1.f : -1.f) / (fabsf(ta) + sqrtf(1.f + ta * ta));
                c = rsqrtf(1.f + tt * tt); sn = tt * c;
            }
            float4 np, nq;
            np.x = c * gp.x - sn * gq.x; nq.x = sn * gp.x + c * gq.x;
            np.y = c * gp.y - sn * gq.y; nq.y = sn * gp.y + c * gq.y;
            np.z = c * gp.z - sn * gq.z; nq.z = sn * gp.z + c * gq.z;
            np.w = c * gp.w - sn * gq.w; nq.w = sn * gp.w + c * gq.w;
            *(float4*)(Gc + p * 20 + ql * 4) = np;
            *(float4*)(Gc + q * 20 + ql * 4) = nq;
            __syncwarp();
        }
    }
}

template<bool TOP>
__device__ void initRow(SM* s, const float* __restrict__ peps, int i, int lane) {
    for (int j = 0; j < 10; j++) {
        stage(s, peps, i, j, lane);
        __syncwarp();
        if (j == 9) {
            if (lane < 16) {
                int ph = lane & 3, il = lane >> 2;
                s->small[9 * 64 + lane] = tslice<TOP>(s, 0, ph, il, 0);
            }
        } else {
            int n = (j == 0) ? 16 : 64;
            for (int e = lane; e < n; e += 32) {
                int ph = e & 3, ic = (e >> 2) & 3, il = e >> 4;
                s->small[j * 64 + e] = tslice<TOP>(s, 0, ph, il, ic);
            }
        }
        __syncwarp();
    }
}

template<bool TOP>
__device__ void compress(SM* s, const float* __restrict__ peps, int i, int lane) {
    // ---- Phase A: right environments ----
    stage(s, peps, i, 9, lane); __syncwarp();
    absorb9<TOP>(s, lane); __syncwarp();
    #pragma unroll
    for (int t = 0; t < 8; t++) {
        int e = lane + 32 * t; int l = e >> 4, l2 = e & 15;
        float acc = 0.f;
        #pragma unroll
        for (int d = 0; d < 4; d++) acc += s->M[l * 4 + d] * s->M[l2 * 4 + d];
        s->F[8 * 256 + e] = acc;
    }
    __syncwarp();
    for (int j = 8; j >= 2; j--) {
        stage(s, peps, i, j, lane); __syncwarp();
        absorbM<TOP>(s, j, lane); __syncwarp();
        envM(s, j, lane);
    }
    // ---- Phase B: left sweep ----
    stage(s, peps, i, 0, lane); __syncwarp();
    absorb0<TOP>(s, lane); __syncwarp();
    if (lane < 16) {
        int b = lane >> 2, d = lane & 3;
        s->small[b * 4 + d] = (b == d) ? 1.f : 0.f;   // site 0: keep-all, U = I gauge
    }
    #pragma unroll
    for (int t = 0; t < 2; t++) {
        int e = lane + 32 * t; int r = e & 15, dd = e >> 4;
        s->sv[dd * 16 + r] = s->M[r * 4 + dd];
    }
    __syncwarp();
    for (int j = 1; j <= 8; j++) {
        stage(s, peps, i, j, lane); __syncwarp();
        absorbM<TOP>(s, j, lane); __syncwarp();
        // m[(a*4+d), r] = sum_b sv[a,b] M[b, r, d]
        #pragma unroll
        for (int t = 0; t < 8; t++) {
            int e = lane + 32 * t; int r = e & 15, rowp = e >> 4;
            int a = rowp >> 2, d = rowp & 3;
            float acc = 0.f;
            #pragma unroll
            for (int b = 0; b < 16; b++) acc += s->sv[a * 16 + b] * s->M[b * 68 + r * 4 + d];
            s->m[rowp * 20 + r] = acc;
        }
        __syncwarp();
        // W = m * F[j] (into T, stride 16)
        const float* Fj = s->F + j * 256;
        #pragma unroll
        for (int t = 0; t < 8; t++) {
            int e = lane + 32 * t; int r = e & 15, rowp = e >> 4;
            float acc = 0.f;
            #pragma unroll
            for (int r2 = 0; r2 < 16; r2++) acc += s->m[rowp * 20 + r2] * Fj[r2 * 16 + r];
            s->T[rowp * 16 + r] = acc;
        }
        __syncwarp();
        // G = W * m^T, stored COLUMN-major (G symmetric)
        #pragma unroll
        for (int t = 0; t < 8; t++) {
            int e = lane + 32 * t; int row2 = e & 15, rowp = e >> 4;
            const float4* Wp = (const float4*)(s->T + rowp * 16);
            const float4* mp = (const float4*)(s->m + row2 * 20);
            float acc = 0.f;
            #pragma unroll
            for (int q = 0; q < 4; q++) {
                float4 wv = Wp[q], mv = mp[q];
                acc += wv.x * mv.x + wv.y * mv.y + wv.z * mv.z + wv.w * mv.w;
            }
            s->G[row2 * 20 + rowp] = acc;
        }
        __syncwarp();
        onesided16(s, lane);
        // column norms^2 = lambda^2
        if (lane < 16) {
            float n2 = 0.f;
            #pragma unroll
            for (int q = 0; q < 4; q++) {
                float4 g = *(float4*)(s->G + lane * 20 + q * 4);
                n2 += g.x * g.x + g.y * g.y + g.z * g.z + g.w * g.w;
            }
            s->cn[lane] = n2;
        }
        __syncwarp();
        if (lane == 0) {
            float dv[16];
            #pragma unroll
            for (int q = 0; q < 16; q++) dv[q] = s->cn[q];
            #pragma unroll
            for (int b = 0; b < 4; b++) {
                int bi = 0; float bv = dv[0];
                #pragma unroll
                for (int q = 1; q < 16; q++) if (dv[q] > bv) { bv = dv[q]; bi = q; }
                s->kidx[b] = bi; dv[bi] = -1.f;
                // column norm = lambda; unit-eigvec scale = 1/lambda, guarded
                s->invn[b] = (bv > 1e-30f) ? rsqrtf(bv) : 0.f;
            }
        }
        __syncwarp();
        // small[j][(a*4+b)*4+d] = u_b[(a*4+d)] = G[:,kidx[b]] * invn[b]
        #pragma unroll
        for (int t = 0; t < 2; t++) {
            int e = lane + 32 * t;
            int d = e & 3, b = (e >> 2) & 3, a = e >> 4;
            s->small[j * 64 + e] = s->G[s->kidx[b] * 20 + (a * 4 + d)] * s->invn[b];
        }
        // sv[b, r] = invn[b] * sum_row G[row, kidx[b]] m[row, r] = u_b^T m
        #pragma unroll
        for (int t = 0; t < 2; t++) {
            int e = lane + 32 * t; int r = e & 15, b = e >> 4;
            int ci = s->kidx[b];
            float acc = 0.f;
            #pragma unroll
            for (int row = 0; row < 16; row++) acc += s->G[ci * 20 + row] * s->m[row * 20 + r];
            s->sv[e] = acc * s->invn[b];
        }
        __syncwarp();
    }
    // site 9
    stage(s, peps, i, 9, lane); __syncwarp();
    absorb9<TOP>(s, lane); __syncwarp();
    if (lane < 16) {
        int d = lane & 3, a = lane >> 2;
        float acc = 0.f;
        #pragma unroll
        for (int b = 0; b < 16; b++) acc += s->sv[a * 16 + b] * s->M[b * 4 + d];
        s->small[9 * 64 + lane] = acc;
    }
    __syncwarp();
    // ---- Phase C: normalize + logn (guarded) ----
    float lacc = 0.f;
    for (int js = 0; js < 10; js++) {
        int n = (js == 0 || js == 9) ? 16 : 64;
        float ss = 0.f;
        for (int e = lane; e < n; e += 32) { float v = s->small[js * 64 + e]; ss += v * v; }
        ss = wsum(ss);
        float nrm = sqrtf(ss);
        float inv = (nrm > 1e-38f) ? (1.f / nrm) : 0.f;
        for (int e = lane; e < n; e += 32) s->small[js * 64 + e] *= inv;
        lacc += logf(fmaxf(nrm, 1e-38f));
    }
    if (lane == 0) s->logn += lacc;
    __syncwarp();
}

extern __shared__ float smraw[];

__global__ void __launch_bounds__(32)
amp_kernel(const int* __restrict__ x, const float* __restrict__ peps, float* __restrict__ out) {
    SM* s = (SM*)smraw;
    int lane = threadIdx.x;
    int blk = blockIdx.x;
    for (int e = lane; e < 100; e += 32) s->xr[e] = x[blk * 100 + e];
    if (lane == 0) s->logn = 0.f;
    __syncwarp();

    initRow<false>(s, peps, 0, lane);
    for (int i = 1; i <= 4; i++) compress<false>(s, peps, i, lane);
    #pragma unroll
    for (int t = 0; t < 20; t++) s->botS[lane + 32 * t] = s->small[lane + 32 * t];
    __syncwarp();

    initRow<true>(s, peps, 9, lane);
    for (int i = 8; i >= 5; i--) compress<true>(s, peps, i, lane);

    // ---- zip ----
    if (lane < 16) {
        int c = lane >> 2, e2 = lane & 3;
        float acc = 0.f;
        #pragma unroll
        for (int d = 0; d < 4; d++) acc += s->botS[c * 4 + d] * s->small[e2 * 4 + d];
        s->Eb[lane] = acc;
    }
    __syncwarp();
    for (int j = 1; j <= 8; j++) {
        if (lane < 16) {
            int c = lane >> 2, e2 = lane & 3;
            float acc = 0.f;
            #pragma unroll
            for (int a = 0; a < 4; a++)
                #pragma unroll
                for (int b = 0; b < 4; b++) {
                    float ev = s->Eb[a * 4 + b];
                    float dot = 0.f;
                    #pragma unroll
                    for (int d = 0; d < 4; d++)
                        dot += s->botS[j * 64 + (a * 4 + c) * 4 + d]
                             * s->small[j * 64 + (b * 4 + e2) * 4 + d];
                    acc += ev * dot;
                }
            s->Eb2[lane] = acc;
        }
        __syncwarp();
        if (lane < 16) s->Eb[lane] = s->Eb2[lane];
        __syncwarp();
    }
    float part = 0.f;
    if (lane < 16) {
        int a = lane >> 2, b = lane & 3;
        float dot = 0.f;
        #pragma unroll
        for (int d = 0; d < 4; d++)
            dot += s->botS[9 * 64 + a * 4 + d] * s->small[9 * 64 + b * 4 + d];
        part = s->Eb[a * 4 + b] * dot;
    }
    part = wsum(part);
    if (lane == 0) out[blk] = part * expf(s->logn);
}

extern "C" void kernel_launch(void* const* d_in, const int* in_sizes, int n_in,
                              void* d_out, int out_size) {
    const int* x;
    const float* peps;
    if (in_sizes[0] == 51200 && n_in >= 2) {
        peps = (const float*)d_in[0];
        x = (const int*)d_in[1];
    } else {
        x = (const int*)d_in[0];
        peps = (const float*)d_in[1];
    }
    float* out = (float*)d_out;
    cudaFuncSetAttribute(amp_kernel, cudaFuncAttributeMaxDynamicSharedMemorySize, (int)sizeof(SM));
    amp_kernel<<<out_size, 32, sizeof(SM)>>>(x, peps, out);
}

// round 8
// speedup vs baseline: 18.6349x; 1.3486x over previous
#include <cuda_runtime.h>
#include <math.h>

// Layouts (identical to the passing R6 kernel):
//  M: raw absorbed middle tensor (16,16,4): [l*68 + r*4 + d]  (stride-68 rows)
//  M site0: [r*4+d] (64); site9: [l*4+d] (64)
//  F: right envs, slot j holds env of bond j (16x16, stride 16), j=1..8
//  m: 16x16, row stride 20.
//  G: COLUMN-major, col stride 20 (G[col*20 + row]) — one-sided Jacobi target.
//  tb: staged peps site slice, linear (v,w,il,ic)

struct SM {
    float F[2304];
    float M[1088];
    float T[1088];      // envM temp (stride 68) / W (16x16, stride 16)
    float tb[256];
    float m[320];
    float G[320];
    float sv[64];
    float small[640];
    float botS[640];
    float Eb[16], Eb2[16];
    float cn[16];
    float invn[4];
    float logn;
    int   kidx[4];
    int   xr[100];
};

__device__ __forceinline__ float wsum(float v) {
    #pragma unroll
    for (int o = 16; o > 0; o >>= 1) v += __shfl_xor_sync(0xffffffffu, v, o);
    return v;
}
__device__ __forceinline__ float wmax(float v) {
    #pragma unroll
    for (int o = 16; o > 0; o >>= 1) v = fmaxf(v, __shfl_xor_sync(0xffffffffu, v, o));
    return v;
}

__device__ __forceinline__ void stage(SM* s, const float* __restrict__ peps, int i, int j, int lane) {
    const float* base = peps + (size_t)(i * 10 + j) * 512;
    int xp = s->xr[i * 10 + j];
    #pragma unroll
    for (int t = 0; t < 8; t++) s->tb[lane + 32 * t] = base[(lane + 32 * t) * 2 + xp];
}

template<bool TOP>
__device__ __forceinline__ float tslice(SM* s, int v, int ph, int il, int ic) {
    int idx = TOP ? (((ph * 4 + v) * 4 + il) * 4 + ic)
                  : (((v * 4 + ph) * 4 + il) * 4 + ic);
    return s->tb[idx];
}

template<bool TOP>
__device__ void absorbM(SM* s, int j, int lane) {
    const float* sm = s->small + j * 64;
    #pragma unroll 4
    for (int t = 0; t < 32; t++) {
        int e = lane + 32 * t;
        int ph = e & 3, r = (e >> 2) & 15, l = e >> 6;
        int a = l >> 2, il = l & 3, b = r >> 2, ic = r & 3;
        const float* mr = sm + (a * 4 + b) * 4;
        float acc = 0.f;
        #pragma unroll
        for (int v = 0; v < 4; v++) acc += mr[v] * tslice<TOP>(s, v, ph, il, ic);
        s->M[l * 68 + r * 4 + ph] = acc;
    }
}

template<bool TOP>
__device__ void absorb0(SM* s, int lane) {
    const float* sm = s->small;
    #pragma unroll
    for (int t = 0; t < 2; t++) {
        int e = lane + 32 * t;
        int ph = e & 3, r = e >> 2;
        int b = r >> 2, ic = r & 3;
        const float* mr = sm + b * 4;
        float acc = 0.f;
        #pragma unroll
        for (int v = 0; v < 4; v++) acc += mr[v] * tslice<TOP>(s, v, ph, 0, ic);
        s->M[e] = acc;  // [r*4+ph]
    }
}

template<bool TOP>
__device__ void absorb9(SM* s, int lane) {
    const float* sm = s->small + 9 * 64;
    #pragma unroll
    for (int t = 0; t < 2; t++) {
        int e = lane + 32 * t;
        int ph = e & 3, l = e >> 2;
        int a = l >> 2, il = l & 3;
        const float* mr = sm + a * 4;
        float acc = 0.f;
        #pragma unroll
        for (int v = 0; v < 4; v++) acc += mr[v] * tslice<TOP>(s, v, ph, il, 0);
        s->M[e] = acc;  // [l*4+ph]
    }
}

// F[j-1] = sum_d M_j F[j] M_j^T (middle sites, M stride 68).
__device__ void envM(SM* s, int j, int lane) {
    const float* Fj = s->F + j * 256;
    #pragma unroll
    for (int g = 0; g < 2; g++) {
        int idx = lane + 32 * g;          // idx = 4*l + d
        int l = idx >> 2, d = idx & 3;
        float Mr[16];
        #pragma unroll
        for (int r2 = 0; r2 < 16; r2++) Mr[r2] = s->M[l * 68 + r2 * 4 + d];
        #pragma unroll 4
        for (int r = 0; r < 16; r++) {
            float acc = 0.f;
            #pragma unroll
            for (int r2 = 0; r2 < 16; r2++) acc += Mr[r2] * Fj[r2 * 16 + r];
            s->T[l * 68 + r * 4 + d] = acc;
        }
    }
    __syncwarp();
    float* Fn = s->F + (j - 1) * 256;
    #pragma unroll
    for (int t = 0; t < 8; t++) {
        int e = lane + 32 * t;
        int l1 = e >> 4, l2 = e & 15;
        const float4* Tp = (const float4*)(s->T + l1 * 68);
        const float4* Mp = (const float4*)(s->M + l2 * 68);
        float acc = 0.f;
        #pragma unroll
        for (int q = 0; q < 16; q++) {
            float4 tv = Tp[q], mv = Mp[q];
            acc += tv.x * mv.x + tv.y * mv.y + tv.z * mv.z + tv.w * mv.w;
        }
        Fn[e] = acc;
    }
    __syncwarp();
}

__device__ __forceinline__ int pairP(int pr, int rnd) {
    return (pr == 0) ? 0 : ((pr - 1 + rnd) % 15) + 1;
}
__device__ __forceinline__ int pairQ(int pr, int rnd) {
    return ((14 - pr + rnd) % 15) + 1;
}

// One-sided Jacobi on G (col-major, stride 20): columns -> lambda_i * u_i.
// Adaptive: exit when max normalized off-dot of a full sweep < 1e-12 (>=2 sweeps, max 6).
__device__ void onesided16(SM* s, int lane) {
    int pr = lane >> 2, ql = lane & 3;
    float* Gc = s->G;
    for (int sw = 0; sw < 6; sw++) {
        float mx = 0.f;
        for (int rnd = 0; rnd < 15; rnd++) {
            int p = pairP(pr, rnd), q = pairQ(pr, rnd);
            float4 gp = *(float4*)(Gc + p * 20 + ql * 4);
            float4 gq = *(float4*)(Gc + q * 20 + ql * 4);
            float dpp = gp.x * gp.x + gp.y * gp.y + gp.z * gp.z + gp.w * gp.w;
            float dqq = gq.x * gq.x + gq.y * gq.y + gq.z * gq.z + gq.w * gq.w;
            float dpq = gp.x * gq.x + gp.y * gq.y + gp.z * gq.z + gp.w * gq.w;
            dpp += __shfl_xor_sync(0xffffffffu, dpp, 1);
            dpp += __shfl_xor_sync(0xffffffffu, dpp, 2);
            dqq += __shfl_xor_sync(0xffffffffu, dqq, 1);
            dqq += __shfl_xor_sync(0xffffffffu, dqq, 2);
            dpq += __shfl_xor_sync(0xffffffffu, dpq, 1);
            dpq += __shfl_xor_sync(0xffffffffu, dpq, 2);
            float den = dpp * dqq;
            float r2 = dpq * dpq;
            mx = fmaxf(mx, r2 / fmaxf(den, 1e-45f));
            float c = 1.f, sn = 0.f;
            if (r2 > 1e-30f * den && r2 > 0.f) {
                float ta = (dqq - dpp) / (2.f * dpq);
                float tt = ((ta >= 0.f) ? 1.f : -1.f) / (fabsf(ta) + sqrtf(1.f + ta * ta));
                c = rsqrtf(1.f + tt * tt); sn = tt * c;
            }
            float4 np, nq;
            np.x = c * gp.x - sn * gq.x; nq.x = sn * gp.x + c * gq.x;
            np.y = c * gp.y - sn * gq.y; nq.y = sn * gp.y + c * gq.y;
            np.z = c * gp.z - sn * gq.z; nq.z = sn * gp.z + c * gq.z;
            np.w = c * gp.w - sn * gq.w; nq.w = sn * gp.w + c * gq.w;
            *(float4*)(Gc + p * 20 + ql * 4) = np;
            *(float4*)(Gc + q * 20 + ql * 4) = nq;
            __syncwarp();
        }
        if (sw >= 1) {
            mx = wmax(mx);
            if (mx < 1e-12f) break;
        }
    }
}

template<bool TOP>
__device__ void initRow(SM* s, const float* __restrict__ peps, int i, int lane) {
    for (int j = 0; j < 10; j++) {
        stage(s, peps, i, j, lane);
        __syncwarp();
        if (j == 9) {
            if (lane < 16) {
                int ph = lane & 3, il = lane >> 2;
                s->small[9 * 64 + lane] = tslice<TOP>(s, 0, ph, il, 0);
            }
        } else {
            int n = (j == 0) ? 16 : 64;
            for (int e = lane; e < n; e += 32) {
                int ph = e & 3, ic = (e >> 2) & 3, il = e >> 4;
                s->small[j * 64 + e] = tslice<TOP>(s, 0, ph, il, ic);
            }
        }
        __syncwarp();
    }
}

template<bool TOP>
__device__ void compress(SM* s, const float* __restrict__ peps, int i, int lane) {
    // ---- Phase A: right environments ----
    stage(s, peps, i, 9, lane); __syncwarp();
    absorb9<TOP>(s, lane); __syncwarp();
    #pragma unroll
    for (int t = 0; t < 8; t++) {
        int e = lane + 32 * t; int l = e >> 4, l2 = e & 15;
        float acc = 0.f;
        #pragma unroll
        for (int d = 0; d < 4; d++) acc += s->M[l * 4 + d] * s->M[l2 * 4 + d];
        s->F[8 * 256 + e] = acc;
    }
    __syncwarp();
    for (int j = 8; j >= 2; j--) {
        stage(s, peps, i, j, lane); __syncwarp();
        absorbM<TOP>(s, j, lane); __syncwarp();
        envM(s, j, lane);
    }
    // ---- Phase B: left sweep ----
    stage(s, peps, i, 0, lane); __syncwarp();
    absorb0<TOP>(s, lane); __syncwarp();
    if (lane < 16) {
        int b = lane >> 2, d = lane & 3;
        s->small[b * 4 + d] = (b == d) ? 1.f : 0.f;   // site 0: keep-all, U = I gauge
    }
    #pragma unroll
    for (int t = 0; t < 2; t++) {
        int e = lane + 32 * t; int r = e & 15, dd = e >> 4;
        s->sv[dd * 16 + r] = s->M[r * 4 + dd];
    }
    __syncwarp();
    for (int j = 1; j <= 8; j++) {
        stage(s, peps, i, j, lane); __syncwarp();
        absorbM<TOP>(s, j, lane); __syncwarp();
        // m[(a*4+d), r] = sum_b sv[a,b] M[b, r, d]
        #pragma unroll
        for (int t = 0; t < 8; t++) {
            int e = lane + 32 * t; int r = e & 15, rowp = e >> 4;
            int a = rowp >> 2, d = rowp & 3;
            float acc = 0.f;
            #pragma unroll
            for (int b = 0; b < 16; b++) acc += s->sv[a * 16 + b] * s->M[b * 68 + r * 4 + d];
            s->m[rowp * 20 + r] = acc;
        }
        __syncwarp();
        // W = m * F[j] (into T, stride 16)
        const float* Fj = s->F + j * 256;
        #pragma unroll
        for (int t = 0; t < 8; t++) {
            int e = lane + 32 * t; int r = e & 15, rowp = e >> 4;
            float acc = 0.f;
            #pragma unroll
            for (int r2 = 0; r2 < 16; r2++) acc += s->m[rowp * 20 + r2] * Fj[r2 * 16 + r];
            s->T[rowp * 16 + r] = acc;
        }
        __syncwarp();
        // G = W * m^T, stored COLUMN-major (G symmetric)
        #pragma unroll
        for (int t = 0; t < 8; t++) {
            int e = lane + 32 * t; int row2 = e & 15, rowp = e >> 4;
            const float4* Wp = (const float4*)(s->T + rowp * 16);
            const float4* mp = (const float4*)(s->m + row2 * 20);
            float acc = 0.f;
            #pragma unroll
            for (int q = 0; q < 4; q++) {
                float4 wv = Wp[q], mv = mp[q];
                acc += wv.x * mv.x + wv.y * mv.y + wv.z * mv.z + wv.w * mv.w;
            }
            s->G[row2 * 20 + rowp] = acc;
        }
        __syncwarp();
        onesided16(s, lane);
        // column norms^2 = lambda^2
        if (lane < 16) {
            float n2 = 0.f;
            #pragma unroll
            for (int q = 0; q < 4; q++) {
                float4 g = *(float4*)(s->G + lane * 20 + q * 4);
                n2 += g.x * g.x + g.y * g.y + g.z * g.z + g.w * g.w;
            }
            s->cn[lane] = n2;
        }
        __syncwarp();
        if (lane == 0) {
            float dv[16];
            #pragma unroll
            for (int q = 0; q < 16; q++) dv[q] = s->cn[q];
            #pragma unroll
            for (int b = 0; b < 4; b++) {
                int bi = 0; float bv = dv[0];
                #pragma unroll
                for (int q = 1; q < 16; q++) if (dv[q] > bv) { bv = dv[q]; bi = q; }
                s->kidx[b] = bi; dv[bi] = -1.f;
                // column norm = lambda; unit-eigvec scale = 1/lambda, guarded
                s->invn[b] = (bv > 1e-30f) ? rsqrtf(bv) : 0.f;
            }
        }
        __syncwarp();
        // small[j][(a*4+b)*4+d] = u_b[(a*4+d)] = G[:,kidx[b]] * invn[b]
        #pragma unroll
        for (int t = 0; t < 2; t++) {
            int e = lane + 32 * t;
            int d = e & 3, b = (e >> 2) & 3, a = e >> 4;
            s->small[j * 64 + e] = s->G[s->kidx[b] * 20 + (a * 4 + d)] * s->invn[b];
        }
        // sv[b, r] = invn[b] * sum_row G[row, kidx[b]] m[row, r] = u_b^T m
        #pragma unroll
        for (int t = 0; t < 2; t++) {
            int e = lane + 32 * t; int r = e & 15, b = e >> 4;
            int ci = s->kidx[b];
            float acc = 0.f;
            #pragma unroll
            for (int row = 0; row < 16; row++) acc += s->G[ci * 20 + row] * s->m[row * 20 + r];
            s->sv[e] = acc * s->invn[b];
        }
        __syncwarp();
    }
    // site 9
    stage(s, peps, i, 9, lane); __syncwarp();
    absorb9<TOP>(s, lane); __syncwarp();
    if (lane < 16) {
        int d = lane & 3, a = lane >> 2;
        float acc = 0.f;
        #pragma unroll
        for (int b = 0; b < 16; b++) acc += s->sv[a * 16 + b] * s->M[b * 4 + d];
        s->small[9 * 64 + lane] = acc;
    }
    __syncwarp();
    // ---- Phase C: normalize + logn (guarded) ----
    float lacc = 0.f;
    for (int js = 0; js < 10; js++) {
        int n = (js == 0 || js == 9) ? 16 : 64;
        float ss = 0.f;
        for (int e = lane; e < n; e += 32) { float v = s->small[js * 64 + e]; ss += v * v; }
        ss = wsum(ss);
        float nrm = sqrtf(ss);
        float inv = (nrm > 1e-38f) ? (1.f / nrm) : 0.f;
        for (int e = lane; e < n; e += 32) s->small[js * 64 + e] *= inv;
        lacc += logf(fmaxf(nrm, 1e-38f));
    }
    if (lane == 0) s->logn += lacc;
    __syncwarp();
}

extern __shared__ float smraw[];

__global__ void __launch_bounds__(32)
amp_kernel(const int* __restrict__ x, const float* __restrict__ peps, float* __restrict__ out) {
    SM* s = (SM*)smraw;
    int lane = threadIdx.x;
    int blk = blockIdx.x;
    for (int e = lane; e < 100; e += 32) s->xr[e] = x[blk * 100 + e];
    if (lane == 0) s->logn = 0.f;
    __syncwarp();

    initRow<false>(s, peps, 0, lane);
    for (int i = 1; i <= 4; i++) compress<false>(s, peps, i, lane);
    #pragma unroll
    for (int t = 0; t < 20; t++) s->botS[lane + 32 * t] = s->small[lane + 32 * t];
    __syncwarp();

    initRow<true>(s, peps, 9, lane);
    for (int i = 8; i >= 5; i--) compress<true>(s, peps, i, lane);

    // ---- zip ----
    if (lane < 16) {
        int c = lane >> 2, e2 = lane & 3;
        float acc = 0.f;
        #pragma unroll
        for (int d = 0; d < 4; d++) acc += s->botS[c * 4 + d] * s->small[e2 * 4 + d];
        s->Eb[lane] = acc;
    }
    __syncwarp();
    for (int j = 1; j <= 8; j++) {
        if (lane < 16) {
            int c = lane >> 2, e2 = lane & 3;
            float acc = 0.f;
            #pragma unroll
            for (int a = 0; a < 4; a++)
                #pragma unroll
                for (int b = 0; b < 4; b++) {
                    float ev = s->Eb[a * 4 + b];
                    float dot = 0.f;
                    #pragma unroll
                    for (int d = 0; d < 4; d++)
                        dot += s->botS[j * 64 + (a * 4 + c) * 4 + d]
                             * s->small[j * 64 + (b * 4 + e2) * 4 + d];
                    acc += ev * dot;
                }
            s->Eb2[lane] = acc;
        }
        __syncwarp();
        if (lane < 16) s->Eb[lane] = s->Eb2[lane];
        __syncwarp();
    }
    float part = 0.f;
    if (lane < 16) {
        int a = lane >> 2, b = lane & 3;
        float dot = 0.f;
        #pragma unroll
        for (int d = 0; d < 4; d++)
            dot += s->botS[9 * 64 + a * 4 + d] * s->small[9 * 64 + b * 4 + d];
        part = s->Eb[a * 4 + b] * dot;
    }
    part = wsum(part);
    if (lane == 0) out[blk] = part * expf(s->logn);
}

extern "C" void kernel_launch(void* const* d_in, const int* in_sizes, int n_in,
                              void* d_out, int out_size) {
    const int* x;
    const float* peps;
    if (in_sizes[0] == 51200 && n_in >= 2) {
        peps = (const float*)d_in[0];
        x = (const int*)d_in[1];
    } else {
        x = (const int*)d_in[0];
        peps = (const float*)d_in[1];
    }
    float* out = (float*)d_out;
    cudaFuncSetAttribute(amp_kernel, cudaFuncAttributeMaxDynamicSharedMemorySize, (int)sizeof(SM));
    amp_kernel<<<out_size, 32, sizeof(SM)>>>(x, peps, out);
}

// round 9
// speedup vs baseline: 22.6175x; 1.2137x over previous
#include <cuda_runtime.h>
#include <math.h>

// Memory plan (temporal aliasing to shrink smem ~27.5KB -> ~20.2KB for occupancy):
//  F[2048]: right envs; env of bond j at slot (j-1)*256, j=1..8 (16x16, stride 16)
//  M[1088]: raw absorbed middle tensor (16,16,4): [l*68 + r*4 + d]; site0/9 flat 64
//  A[1088]: arena.
//    Phase A: T (stride-68 env temp) = A[0..1087]; tb = A[320..575] (dead before T written)
//    Phase B: m = A[0..319] (stride 20), W = A[320..575] (stride 16, aliases dead tb),
//             G = A[576..895] (col-major stride 20), sv = A[896..959]
//    Zip:     botS register dump = A[0..639]
//  small[640]: compressed MPS. botS lives in 20 registers across the top half.

struct SM {
    float F[2048];
    float M[1088];
    float A[1088];
    float small[640];
    float Eb[16], Eb2[16];
    float cn[16];
    float invn[4];
    float logn;
    int   kidx[4];
    int   xr[100];
};

__device__ __forceinline__ float wsum(float v) {
    #pragma unroll
    for (int o = 16; o > 0; o >>= 1) v += __shfl_xor_sync(0xffffffffu, v, o);
    return v;
}
__device__ __forceinline__ float wmax(float v) {
    #pragma unroll
    for (int o = 16; o > 0; o >>= 1) v = fmaxf(v, __shfl_xor_sync(0xffffffffu, v, o));
    return v;
}

// tb = A + 320 (256 floats), linear (v,w,il,ic)
__device__ __forceinline__ void stage(SM* s, const float* __restrict__ peps, int i, int j, int lane) {
    const float* base = peps + (size_t)(i * 10 + j) * 512;
    int xp = s->xr[i * 10 + j];
    float* tb = s->A + 320;
    #pragma unroll
    for (int t = 0; t < 8; t++) tb[lane + 32 * t] = base[(lane + 32 * t) * 2 + xp];
}

template<bool TOP>
__device__ __forceinline__ float tslice(SM* s, int v, int ph, int il, int ic) {
    int idx = TOP ? (((ph * 4 + v) * 4 + il) * 4 + ic)
                  : (((v * 4 + ph) * 4 + il) * 4 + ic);
    return s->A[320 + idx];
}

template<bool TOP>
__device__ void absorbM(SM* s, int j, int lane) {
    const float* sm = s->small + j * 64;
    #pragma unroll 4
    for (int t = 0; t < 32; t++) {
        int e = lane + 32 * t;
        int ph = e & 3, r = (e >> 2) & 15, l = e >> 6;
        int a = l >> 2, il = l & 3, b = r >> 2, ic = r & 3;
        const float* mr = sm + (a * 4 + b) * 4;
        float acc = 0.f;
        #pragma unroll
        for (int v = 0; v < 4; v++) acc += mr[v] * tslice<TOP>(s, v, ph, il, ic);
        s->M[l * 68 + r * 4 + ph] = acc;
    }
}

template<bool TOP>
__device__ void absorb0(SM* s, int lane) {
    const float* sm = s->small;
    #pragma unroll
    for (int t = 0; t < 2; t++) {
        int e = lane + 32 * t;
        int ph = e & 3, r = e >> 2;
        int b = r >> 2, ic = r & 3;
        const float* mr = sm + b * 4;
        float acc = 0.f;
        #pragma unroll
        for (int v = 0; v < 4; v++) acc += mr[v] * tslice<TOP>(s, v, ph, 0, ic);
        s->M[e] = acc;  // [r*4+ph]
    }
}

template<bool TOP>
__device__ void absorb9(SM* s, int lane) {
    const float* sm = s->small + 9 * 64;
    #pragma unroll
    for (int t = 0; t < 2; t++) {
        int e = lane + 32 * t;
        int ph = e & 3, l = e >> 2;
        int a = l >> 2, il = l & 3;
        const float* mr = sm + a * 4;
        float acc = 0.f;
        #pragma unroll
        for (int v = 0; v < 4; v++) acc += mr[v] * tslice<TOP>(s, v, ph, il, 0);
        s->M[e] = acc;  // [l*4+ph]
    }
}

// env(bond j-1) = sum_d M_j env(bond j) M_j^T.  T = arena (stride 68).
__device__ void envM(SM* s, int j, int lane) {
    const float* Fj = s->F + (j - 1) * 256;
    float* T = s->A;
    #pragma unroll
    for (int g = 0; g < 2; g++) {
        int idx = lane + 32 * g;          // idx = 4*l + d
        int l = idx >> 2, d = idx & 3;
        float Mr[16];
        #pragma unroll
        for (int r2 = 0; r2 < 16; r2++) Mr[r2] = s->M[l * 68 + r2 * 4 + d];
        #pragma unroll 4
        for (int r = 0; r < 16; r++) {
            float acc = 0.f;
            #pragma unroll
            for (int r2 = 0; r2 < 16; r2++) acc += Mr[r2] * Fj[r2 * 16 + r];
            T[l * 68 + r * 4 + d] = acc;
        }
    }
    __syncwarp();
    float* Fn = s->F + (j - 2) * 256;
    #pragma unroll
    for (int t = 0; t < 8; t++) {
        int e = lane + 32 * t;
        int l1 = e >> 4, l2 = e & 15;
        const float4* Tp = (const float4*)(T + l1 * 68);
        const float4* Mp = (const float4*)(s->M + l2 * 68);
        float acc = 0.f;
        #pragma unroll
        for (int q = 0; q < 16; q++) {
            float4 tv = Tp[q], mv = Mp[q];
            acc += tv.x * mv.x + tv.y * mv.y + tv.z * mv.z + tv.w * mv.w;
        }
        Fn[e] = acc;
    }
    __syncwarp();
}

__device__ __forceinline__ int pairP(int pr, int rnd) {
    return (pr == 0) ? 0 : ((pr - 1 + rnd) % 15) + 1;
}
__device__ __forceinline__ int pairQ(int pr, int rnd) {
    return ((14 - pr + rnd) % 15) + 1;
}

// One-sided Jacobi on G (col-major, stride 20, at A+576): columns -> lambda_i * u_i.
__device__ void onesided16(SM* s, int lane) {
    int pr = lane >> 2, ql = lane & 3;
    float* Gc = s->A + 576;
    for (int sw = 0; sw < 6; sw++) {
        float mx = 0.f;
        for (int rnd = 0; rnd < 15; rnd++) {
            int p = pairP(pr, rnd), q = pairQ(pr, rnd);
            float4 gp = *(float4*)(Gc + p * 20 + ql * 4);
            float4 gq = *(float4*)(Gc + q * 20 + ql * 4);
            float dpp = gp.x * gp.x + gp.y * gp.y + gp.z * gp.z + gp.w * gp.w;
            float dqq = gq.x * gq.x + gq.y * gq.y + gq.z * gq.z + gq.w * gq.w;
            float dpq = gp.x * gq.x + gp.y * gq.y + gp.z * gq.z + gp.w * gq.w;
            dpp += __shfl_xor_sync(0xffffffffu, dpp, 1);
            dpp += __shfl_xor_sync(0xffffffffu, dpp, 2);
            dqq += __shfl_xor_sync(0xffffffffu, dqq, 1);
            dqq += __shfl_xor_sync(0xffffffffu, dqq, 2);
            dpq += __shfl_xor_sync(0xffffffffu, dpq, 1);
            dpq += __shfl_xor_sync(0xffffffffu, dpq, 2);
            float den = dpp * dqq;
            float r2 = dpq * dpq;
            mx = fmaxf(mx, r2 / fmaxf(den, 1e-45f));
            float c = 1.f, sn = 0.f;
            if (r2 > 1e-30f * den && r2 > 0.f) {
                float ta = (dqq - dpp) / (2.f * dpq);
                float tt = ((ta >= 0.f) ? 1.f : -1.f) / (fabsf(ta) + sqrtf(1.f + ta * ta));
                c = rsqrtf(1.f + tt * tt); sn = tt * c;
            }
            float4 np, nq;
            np.x = c * gp.x - sn * gq.x; nq.x = sn * gp.x + c * gq.x;
            np.y = c * gp.y - sn * gq.y; nq.y = sn * gp.y + c * gq.y;
            np.z = c * gp.z - sn * gq.z; nq.z = sn * gp.z + c * gq.z;
            np.w = c * gp.w - sn * gq.w; nq.w = sn * gp.w + c * gq.w;
            *(float4*)(Gc + p * 20 + ql * 4) = np;
            *(float4*)(Gc + q * 20 + ql * 4) = nq;
            __syncwarp();
        }
        if (sw >= 1) {
            mx = wmax(mx);
            if (mx < 1e-12f) break;
        }
    }
}

template<bool TOP>
__device__ void initRow(SM* s, const float* __restrict__ peps, int i, int lane) {
    for (int j = 0; j < 10; j++) {
        stage(s, peps, i, j, lane);
        __syncwarp();
        if (j == 9) {
            if (lane < 16) {
                int ph = lane & 3, il = lane >> 2;
                s->small[9 * 64 + lane] = tslice<TOP>(s, 0, ph, il, 0);
            }
        } else {
            int n = (j == 0) ? 16 : 64;
            for (int e = lane; e < n; e += 32) {
                int ph = e & 3, ic = (e >> 2) & 3, il = e >> 4;
                s->small[j * 64 + e] = tslice<TOP>(s, 0, ph, il, ic);
            }
        }
        __syncwarp();
    }
}

template<bool TOP>
__device__ void compress(SM* s, const float* __restrict__ peps, int i, int lane) {
    float* m  = s->A;          // stride 20
    float* W  = s->A + 320;    // stride 16
    float* G  = s->A + 576;    // col-major stride 20
    float* sv = s->A + 896;
    // ---- Phase A: right environments ----
    stage(s, peps, i, 9, lane); __syncwarp();
    absorb9<TOP>(s, lane); __syncwarp();
    #pragma unroll
    for (int t = 0; t < 8; t++) {
        int e = lane + 32 * t; int l = e >> 4, l2 = e & 15;
        float acc = 0.f;
        #pragma unroll
        for (int d = 0; d < 4; d++) acc += s->M[l * 4 + d] * s->M[l2 * 4 + d];
        s->F[7 * 256 + e] = acc;   // env of bond 8 at slot 7
    }
    __syncwarp();
    for (int j = 8; j >= 2; j--) {
        stage(s, peps, i, j, lane); __syncwarp();
        absorbM<TOP>(s, j, lane); __syncwarp();
        envM(s, j, lane);
    }
    // ---- Phase B: left sweep ----
    stage(s, peps, i, 0, lane); __syncwarp();
    absorb0<TOP>(s, lane); __syncwarp();
    if (lane < 16) {
        int b = lane >> 2, d = lane & 3;
        s->small[b * 4 + d] = (b == d) ? 1.f : 0.f;   // site 0: keep-all, U = I gauge
    }
    #pragma unroll
    for (int t = 0; t < 2; t++) {
        int e = lane + 32 * t; int r = e & 15, dd = e >> 4;
        sv[dd * 16 + r] = s->M[r * 4 + dd];
    }
    __syncwarp();
    for (int j = 1; j <= 8; j++) {
        stage(s, peps, i, j, lane); __syncwarp();
        absorbM<TOP>(s, j, lane); __syncwarp();
        // m[(a*4+d), r] = sum_b sv[a,b] M[b, r, d]
        #pragma unroll
        for (int t = 0; t < 8; t++) {
            int e = lane + 32 * t; int r = e & 15, rowp = e >> 4;
            int a = rowp >> 2, d = rowp & 3;
            float acc = 0.f;
            #pragma unroll
            for (int b = 0; b < 16; b++) acc += sv[a * 16 + b] * s->M[b * 68 + r * 4 + d];
            m[rowp * 20 + r] = acc;
        }
        __syncwarp();
        // W = m * F[bond j]   (W aliases dead tb)
        const float* Fj = s->F + (j - 1) * 256;
        #pragma unroll
        for (int t = 0; t < 8; t++) {
            int e = lane + 32 * t; int r = e & 15, rowp = e >> 4;
            float acc = 0.f;
            #pragma unroll
            for (int r2 = 0; r2 < 16; r2++) acc += m[rowp * 20 + r2] * Fj[r2 * 16 + r];
            W[rowp * 16 + r] = acc;
        }
        __syncwarp();
        // G = W * m^T, stored COLUMN-major (G symmetric)
        #pragma unroll
        for (int t = 0; t < 8; t++) {
            int e = lane + 32 * t; int row2 = e & 15, rowp = e >> 4;
            const float4* Wp = (const float4*)(W + rowp * 16);
            const float4* mp = (const float4*)(m + row2 * 20);
            float acc = 0.f;
            #pragma unroll
            for (int q = 0; q < 4; q++) {
                float4 wv = Wp[q], mv = mp[q];
                acc += wv.x * mv.x + wv.y * mv.y + wv.z * mv.z + wv.w * mv.w;
            }
            G[row2 * 20 + rowp] = acc;
        }
        __syncwarp();
        onesided16(s, lane);
        // column norms^2 = lambda^2
        if (lane < 16) {
            float n2 = 0.f;
            #pragma unroll
            for (int q = 0; q < 4; q++) {
                float4 g = *(float4*)(G + lane * 20 + q * 4);
                n2 += g.x * g.x + g.y * g.y + g.z * g.z + g.w * g.w;
            }
            s->cn[lane] = n2;
        }
        __syncwarp();
        if (lane == 0) {
            float dv[16];
            #pragma unroll
            for (int q = 0; q < 16; q++) dv[q] = s->cn[q];
            #pragma unroll
            for (int b = 0; b < 4; b++) {
                int bi = 0; float bv = dv[0];
                #pragma unroll
                for (int q = 1; q < 16; q++) if (dv[q] > bv) { bv = dv[q]; bi = q; }
                s->kidx[b] = bi; dv[bi] = -1.f;
                s->invn[b] = (bv > 1e-30f) ? rsqrtf(bv) : 0.f;
            }
        }
        __syncwarp();
        // small[j][(a*4+b)*4+d] = u_b[(a*4+d)] = G[:,kidx[b]] * invn[b]
        #pragma unroll
        for (int t = 0; t < 2; t++) {
            int e = lane + 32 * t;
            int d = e & 3, b = (e >> 2) & 3, a = e >> 4;
            s->small[j * 64 + e] = G[s->kidx[b] * 20 + (a * 4 + d)] * s->invn[b];
        }
        __syncwarp();
        // sv[b, r] = invn[b] * sum_row G[row, kidx[b]] m[row, r] = u_b^T m
        #pragma unroll
        for (int t = 0; t < 2; t++) {
            int e = lane + 32 * t; int r = e & 15, b = e >> 4;
            int ci = s->kidx[b];
            float acc = 0.f;
            #pragma unroll
            for (int row = 0; row < 16; row++) acc += G[ci * 20 + row] * m[row * 20 + r];
            sv[e] = acc * s->invn[b];
        }
        __syncwarp();
    }
    // site 9
    stage(s, peps, i, 9, lane); __syncwarp();
    absorb9<TOP>(s, lane); __syncwarp();
    if (lane < 16) {
        int d = lane & 3, a = lane >> 2;
        float acc = 0.f;
        #pragma unroll
        for (int b = 0; b < 16; b++) acc += sv[a * 16 + b] * s->M[b * 4 + d];
        s->small[9 * 64 + lane] = acc;
    }
    __syncwarp();
    // ---- Phase C: normalize + logn (guarded) ----
    float lacc = 0.f;
    for (int js = 0; js < 10; js++) {
        int n = (js == 0 || js == 9) ? 16 : 64;
        float ss = 0.f;
        for (int e = lane; e < n; e += 32) { float v = s->small[js * 64 + e]; ss += v * v; }
        ss = wsum(ss);
        float nrm = sqrtf(ss);
        float inv = (nrm > 1e-38f) ? (1.f / nrm) : 0.f;
        for (int e = lane; e < n; e += 32) s->small[js * 64 + e] *= inv;
        lacc += logf(fmaxf(nrm, 1e-38f));
    }
    if (lane == 0) s->logn += lacc;
    __syncwarp();
}

extern __shared__ float smraw[];

__global__ void __launch_bounds__(32)
amp_kernel(const int* __restrict__ x, const float* __restrict__ peps, float* __restrict__ out) {
    SM* s = (SM*)smraw;
    int lane = threadIdx.x;
    int blk = blockIdx.x;
    for (int e = lane; e < 100; e += 32) s->xr[e] = x[blk * 100 + e];
    if (lane == 0) s->logn = 0.f;
    __syncwarp();

    initRow<false>(s, peps, 0, lane);
    for (int i = 1; i <= 4; i++) compress<false>(s, peps, i, lane);
    // bottom compressed MPS -> registers (smem saved for occupancy)
    float br[20];
    #pragma unroll
    for (int t = 0; t < 20; t++) br[t] = s->small[lane + 32 * t];
    __syncwarp();

    initRow<true>(s, peps, 9, lane);
    for (int i = 8; i >= 5; i--) compress<true>(s, peps, i, lane);

    // dump bottom MPS into the (dead) arena for random-access in the zip
    float* botS = s->A;
    #pragma unroll
    for (int t = 0; t < 20; t++) botS[lane + 32 * t] = br[t];
    __syncwarp();

    // ---- zip ----
    if (lane < 16) {
        int c = lane >> 2, e2 = lane & 3;
        float acc = 0.f;
        #pragma unroll
        for (int d = 0; d < 4; d++) acc += botS[c * 4 + d] * s->small[e2 * 4 + d];
        s->Eb[lane] = acc;
    }
    __syncwarp();
    for (int j = 1; j <= 8; j++) {
        if (lane < 16) {
            int c = lane >> 2, e2 = lane & 3;
            float acc = 0.f;
            #pragma unroll
            for (int a = 0; a < 4; a++)
                #pragma unroll
                for (int b = 0; b < 4; b++) {
                    float ev = s->Eb[a * 4 + b];
                    float dot = 0.f;
                    #pragma unroll
                    for (int d = 0; d < 4; d++)
                        dot += botS[j * 64 + (a * 4 + c) * 4 + d]
                             * s->small[j * 64 + (b * 4 + e2) * 4 + d];
                    acc += ev * dot;
                }
            s->Eb2[lane] = acc;
        }
        __syncwarp();
        if (lane < 16) s->Eb[lane] = s->Eb2[lane];
        __syncwarp();
    }
    float part = 0.f;
    if (lane < 16) {
        int a = lane >> 2, b = lane & 3;
        float dot = 0.f;
        #pragma unroll
        for (int d = 0; d < 4; d++)
            dot += botS[9 * 64 + a * 4 + d] * s->small[9 * 64 + b * 4 + d];
        part = s->Eb[a * 4 + b] * dot;
    }
    part = wsum(part);
    if (lane == 0) out[blk] = part * expf(s->logn);
}

extern "C" void kernel_launch(void* const* d_in, const int* in_sizes, int n_in,
                              void* d_out, int out_size) {
    const int* x;
    const float* peps;
    if (in_sizes[0] == 51200 && n_in >= 2) {
        peps = (const float*)d_in[0];
        x = (const int*)d_in[1];
    } else {
        x = (const int*)d_in[0];
        peps = (const float*)d_in[1];
    }
    float* out = (float*)d_out;
    cudaFuncSetAttribute(amp_kernel, cudaFuncAttributeMaxDynamicSharedMemorySize, (int)sizeof(SM));
    amp_kernel<<<out_size, 32, sizeof(SM)>>>(x, peps, out);
}

// round 10
// speedup vs baseline: 23.4380x; 1.0363x over previous
#include <cuda_runtime.h>
#include <math.h>

// Memory plan (~20.2KB smem):
//  F[2048]: right envs; env of bond j at slot (j-1)*256, j=1..8 (16x16, stride 16)
//  M[1088]: raw absorbed middle tensor (16,16,4): [l*68 + r*4 + d]; site0/9 flat 64
//  A[1088]: arena.
//    Phase A: T (stride-68 env temp) = A[0..1087]; tb = A[320..575]
//    Phase B: m = A[0..319] (stride 20), W = A[320..575] (stride 16),
//             G = A[576..895] (col-major stride 20), sv = A[896..959]
//    Zip:     botS register dump = A[0..639]

struct SM {
    float F[2048];
    float M[1088];
    float A[1088];
    float small[640];
    float Eb[16], Eb2[16];
    float cn[16];
    float invn[4];
    float logn;
    int   kidx[4];
    int   xr[100];
};

__device__ __forceinline__ float wsum(float v) {
    #pragma unroll
    for (int o = 16; o > 0; o >>= 1) v += __shfl_xor_sync(0xffffffffu, v, o);
    return v;
}
__device__ __forceinline__ float wmax(float v) {
    #pragma unroll
    for (int o = 16; o > 0; o >>= 1) v = fmaxf(v, __shfl_xor_sync(0xffffffffu, v, o));
    return v;
}
__device__ __forceinline__ float d4(float4 a, float4 b) {
    return a.x * b.x + a.y * b.y + a.z * b.z + a.w * b.w;
}

// tb = A + 320 (256 floats), linear (v,w,il,ic)
__device__ __forceinline__ void stage(SM* s, const float* __restrict__ peps, int i, int j, int lane) {
    const float* base = peps + (size_t)(i * 10 + j) * 512;
    int xp = s->xr[i * 10 + j];
    float* tb = s->A + 320;
    #pragma unroll
    for (int t = 0; t < 8; t++) tb[lane + 32 * t] = base[(lane + 32 * t) * 2 + xp];
}

template<bool TOP>
__device__ __forceinline__ float tslice(SM* s, int v, int ph, int il, int ic) {
    int idx = TOP ? (((ph * 4 + v) * 4 + il) * 4 + ic)
                  : (((v * 4 + ph) * 4 + il) * 4 + ic);
    return s->A[320 + idx];
}

template<bool TOP>
__device__ void absorbM(SM* s, int j, int lane) {
    const float* sm = s->small + j * 64;
    #pragma unroll 4
    for (int t = 0; t < 32; t++) {
        int e = lane + 32 * t;
        int ph = e & 3, r = (e >> 2) & 15, l = e >> 6;
        int a = l >> 2, il = l & 3, b = r >> 2, ic = r & 3;
        const float* mr = sm + (a * 4 + b) * 4;
        float acc = 0.f;
        #pragma unroll
        for (int v = 0; v < 4; v++) acc += mr[v] * tslice<TOP>(s, v, ph, il, ic);
        s->M[l * 68 + r * 4 + ph] = acc;
    }
}

template<bool TOP>
__device__ void absorb0(SM* s, int lane) {
    const float* sm = s->small;
    #pragma unroll
    for (int t = 0; t < 2; t++) {
        int e = lane + 32 * t;
        int ph = e & 3, r = e >> 2;
        int b = r >> 2, ic = r & 3;
        const float* mr = sm + b * 4;
        float acc = 0.f;
        #pragma unroll
        for (int v = 0; v < 4; v++) acc += mr[v] * tslice<TOP>(s, v, ph, 0, ic);
        s->M[e] = acc;  // [r*4+ph]
    }
}

template<bool TOP>
__device__ void absorb9(SM* s, int lane) {
    const float* sm = s->small + 9 * 64;
    #pragma unroll
    for (int t = 0; t < 2; t++) {
        int e = lane + 32 * t;
        int ph = e & 3, l = e >> 2;
        int a = l >> 2, il = l & 3;
        const float* mr = sm + a * 4;
        float acc = 0.f;
        #pragma unroll
        for (int v = 0; v < 4; v++) acc += mr[v] * tslice<TOP>(s, v, ph, il, 0);
        s->M[e] = acc;  // [l*4+ph]
    }
}

// env(bond j-1) = sum_d M_j env(bond j) M_j^T.
__device__ void envM(SM* s, int j, int lane) {
    const float* Fj = s->F + (j - 1) * 256;
    float* T = s->A;
    #pragma unroll
    for (int g = 0; g < 2; g++) {
        int idx = lane + 32 * g;          // idx = 4*l + d
        int l = idx >> 2, d = idx & 3;
        float Mr[16];
        #pragma unroll
        for (int r2 = 0; r2 < 16; r2++) Mr[r2] = s->M[l * 68 + r2 * 4 + d];
        #pragma unroll 4
        for (int r = 0; r < 16; r++) {
            float acc = 0.f;
            #pragma unroll
            for (int r2 = 0; r2 < 16; r2++) acc += Mr[r2] * Fj[r2 * 16 + r];
            T[l * 68 + r * 4 + d] = acc;
        }
    }
    __syncwarp();
    // stage2: register-tiled 2x4 outputs per lane.
    float* Fn = s->F + (j - 2) * 256;
    {
        int pr2 = lane >> 2, qd = lane & 3;
        int l1a = 2 * pr2;
        const float4* Ta = (const float4*)(T + l1a * 68);
        const float4* Tb = (const float4*)(T + (l1a + 1) * 68);
        const float4* M0 = (const float4*)(s->M + (4 * qd + 0) * 68);
        const float4* M1 = (const float4*)(s->M + (4 * qd + 1) * 68);
        const float4* M2 = (const float4*)(s->M + (4 * qd + 2) * 68);
        const float4* M3 = (const float4*)(s->M + (4 * qd + 3) * 68);
        float a0 = 0.f, a1 = 0.f, a2 = 0.f, a3 = 0.f;
        float b0 = 0.f, b1 = 0.f, b2 = 0.f, b3 = 0.f;
        #pragma unroll
        for (int q = 0; q < 16; q++) {
            float4 ta = Ta[q], tb = Tb[q];
            float4 m0 = M0[q]; a0 += d4(ta, m0); b0 += d4(tb, m0);
            float4 m1 = M1[q]; a1 += d4(ta, m1); b1 += d4(tb, m1);
            float4 m2 = M2[q]; a2 += d4(ta, m2); b2 += d4(tb, m2);
            float4 m3 = M3[q]; a3 += d4(ta, m3); b3 += d4(tb, m3);
        }
        *(float4*)(Fn + l1a * 16 + 4 * qd)       = make_float4(a0, a1, a2, a3);
        *(float4*)(Fn + (l1a + 1) * 16 + 4 * qd) = make_float4(b0, b1, b2, b3);
    }
    __syncwarp();
}

__device__ __forceinline__ int pairP(int pr, int rnd) {
    return (pr == 0) ? 0 : ((pr - 1 + rnd) % 15) + 1;
}
__device__ __forceinline__ int pairQ(int pr, int rnd) {
    return ((14 - pr + rnd) % 15) + 1;
}

// One-sided Jacobi on G (col-major, stride 20, at A+576): columns -> lambda_i * u_i.
__device__ void onesided16(SM* s, int lane) {
    int pr = lane >> 2, ql = lane & 3;
    float* Gc = s->A + 576;
    for (int sw = 0; sw < 6; sw++) {
        float mx = 0.f;
        for (int rnd = 0; rnd < 15; rnd++) {
            int p = pairP(pr, rnd), q = pairQ(pr, rnd);
            float4 gp = *(float4*)(Gc + p * 20 + ql * 4);
            float4 gq = *(float4*)(Gc + q * 20 + ql * 4);
            float dpp = gp.x * gp.x + gp.y * gp.y + gp.z * gp.z + gp.w * gp.w;
            float dqq = gq.x * gq.x + gq.y * gq.y + gq.z * gq.z + gq.w * gq.w;
            float dpq = gp.x * gq.x + gp.y * gq.y + gp.z * gq.z + gp.w * gq.w;
            dpp += __shfl_xor_sync(0xffffffffu, dpp, 1);
            dpp += __shfl_xor_sync(0xffffffffu, dpp, 2);
            dqq += __shfl_xor_sync(0xffffffffu, dqq, 1);
            dqq += __shfl_xor_sync(0xffffffffu, dqq, 2);
            dpq += __shfl_xor_sync(0xffffffffu, dpq, 1);
            dpq += __shfl_xor_sync(0xffffffffu, dpq, 2);
            float den = dpp * dqq;
            float r2 = dpq * dpq;
            mx = fmaxf(mx, r2 / fmaxf(den, 1e-45f));
            float c = 1.f, sn = 0.f;
            if (r2 > 1e-30f * den && r2 > 0.f) {
                float ta = (dqq - dpp) / (2.f * dpq);
                float tt = ((ta >= 0.f) ? 1.f : -1.f) / (fabsf(ta) + sqrtf(1.f + ta * ta));
                c = rsqrtf(1.f + tt * tt); sn = tt * c;
            }
            float4 np, nq;
            np.x = c * gp.x - sn * gq.x; nq.x = sn * gp.x + c * gq.x;
            np.y = c * gp.y - sn * gq.y; nq.y = sn * gp.y + c * gq.y;
            np.z = c * gp.z - sn * gq.z; nq.z = sn * gp.z + c * gq.z;
            np.w = c * gp.w - sn * gq.w; nq.w = sn * gp.w + c * gq.w;
            *(float4*)(Gc + p * 20 + ql * 4) = np;
            *(float4*)(Gc + q * 20 + ql * 4) = nq;
            __syncwarp();
        }
        if (sw >= 1) {
            mx = wmax(mx);
            if (mx < 1e-12f) break;
        }
    }
}

template<bool TOP>
__device__ void initRow(SM* s, const float* __restrict__ peps, int i, int lane) {
    for (int j = 0; j < 10; j++) {
        stage(s, peps, i, j, lane);
        __syncwarp();
        if (j == 9) {
            if (lane < 16) {
                int ph = lane & 3, il = lane >> 2;
                s->small[9 * 64 + lane] = tslice<TOP>(s, 0, ph, il, 0);
            }
        } else {
            int n = (j == 0) ? 16 : 64;
            for (int e = lane; e < n; e += 32) {
                int ph = e & 3, ic = (e >> 2) & 3, il = e >> 4;
                s->small[j * 64 + e] = tslice<TOP>(s, 0, ph, il, ic);
            }
        }
        __syncwarp();
    }
}

template<bool TOP>
__device__ void compress(SM* s, const float* __restrict__ peps, int i, int lane) {
    float* m  = s->A;          // stride 20
    float* W  = s->A + 320;    // stride 16
    float* G  = s->A + 576;    // col-major stride 20
    float* sv = s->A + 896;
    int rfix = lane & 15;
    int hw = lane >> 4;
    // ---- Phase A: right environments ----
    stage(s, peps, i, 9, lane); __syncwarp();
    absorb9<TOP>(s, lane); __syncwarp();
    #pragma unroll
    for (int t = 0; t < 8; t++) {
        int e = lane + 32 * t; int l = e >> 4, l2 = e & 15;
        float acc = 0.f;
        #pragma unroll
        for (int d = 0; d < 4; d++) acc += s->M[l * 4 + d] * s->M[l2 * 4 + d];
        s->F[7 * 256 + e] = acc;   // env of bond 8 at slot 7
    }
    __syncwarp();
    for (int j = 8; j >= 2; j--) {
        stage(s, peps, i, j, lane); __syncwarp();
        absorbM<TOP>(s, j, lane); __syncwarp();
        envM(s, j, lane);
    }
    // ---- Phase B: left sweep ----
    stage(s, peps, i, 0, lane); __syncwarp();
    absorb0<TOP>(s, lane); __syncwarp();
    if (lane < 16) {
        int b = lane >> 2, d = lane & 3;
        s->small[b * 4 + d] = (b == d) ? 1.f : 0.f;   // site 0: keep-all, U = I gauge
    }
    #pragma unroll
    for (int t = 0; t < 2; t++) {
        int e = lane + 32 * t; int r = e & 15, dd = e >> 4;
        sv[dd * 16 + r] = s->M[r * 4 + dd];
    }
    __syncwarp();
    for (int j = 1; j <= 8; j++) {
        stage(s, peps, i, j, lane); __syncwarp();
        absorbM<TOP>(s, j, lane); __syncwarp();
        // m[(a*4+d), r] = sum_b sv[a,b] M[b, r, d]
        #pragma unroll
        for (int t = 0; t < 8; t++) {
            int e = lane + 32 * t; int r = e & 15, rowp = e >> 4;
            int a = rowp >> 2, d = rowp & 3;
            float acc = 0.f;
            #pragma unroll
            for (int b = 0; b < 16; b++) acc += sv[a * 16 + b] * s->M[b * 68 + r * 4 + d];
            m[rowp * 20 + r] = acc;
        }
        __syncwarp();
        // W = m * F[bond j]: cache this lane's F column (r = lane&15 invariant)
        {
            const float* Fj = s->F + (j - 1) * 256;
            float Fc[16];
            #pragma unroll
            for (int r2 = 0; r2 < 16; r2++) Fc[r2] = Fj[r2 * 16 + rfix];
            #pragma unroll
            for (int t = 0; t < 8; t++) {
                int rowp = hw + 2 * t;
                const float4* mr = (const float4*)(m + rowp * 20);
                float4 m0 = mr[0], m1 = mr[1], m2 = mr[2], m3 = mr[3];
                float acc = m0.x * Fc[0] + m0.y * Fc[1] + m0.z * Fc[2] + m0.w * Fc[3]
                          + m1.x * Fc[4] + m1.y * Fc[5] + m1.z * Fc[6] + m1.w * Fc[7]
                          + m2.x * Fc[8] + m2.y * Fc[9] + m2.z * Fc[10] + m2.w * Fc[11]
                          + m3.x * Fc[12] + m3.y * Fc[13] + m3.z * Fc[14] + m3.w * Fc[15];
                W[rowp * 16 + rfix] = acc;
            }
        }
        __syncwarp();
        // G = W * m^T (col-major): cache this lane's m row (row2 = lane&15 invariant)
        {
            const float4* mr = (const float4*)(m + rfix * 20);
            float4 c0 = mr[0], c1 = mr[1], c2 = mr[2], c3 = mr[3];
            #pragma unroll
            for (int t = 0; t < 8; t++) {
                int rowp = hw + 2 * t;
                const float4* Wp = (const float4*)(W + rowp * 16);
                float acc = d4(Wp[0], c0) + d4(Wp[1], c1) + d4(Wp[2], c2) + d4(Wp[3], c3);
                G[rfix * 20 + rowp] = acc;
            }
        }
        __syncwarp();
        onesided16(s, lane);
        // column norms^2 = lambda^2
        if (lane < 16) {
            float n2 = 0.f;
            #pragma unroll
            for (int q = 0; q < 4; q++) {
                float4 g = *(float4*)(G + lane * 20 + q * 4);
                n2 += g.x * g.x + g.y * g.y + g.z * g.z + g.w * g.w;
            }
            s->cn[lane] = n2;
        }
        __syncwarp();
        if (lane == 0) {
            float dv[16];
            #pragma unroll
            for (int q = 0; q < 16; q++) dv[q] = s->cn[q];
            #pragma unroll
            for (int b = 0; b < 4; b++) {
                int bi = 0; float bv = dv[0];
                #pragma unroll
                for (int q = 1; q < 16; q++) if (dv[q] > bv) { bv = dv[q]; bi = q; }
                s->kidx[b] = bi; dv[bi] = -1.f;
                s->invn[b] = (bv > 1e-30f) ? rsqrtf(bv) : 0.f;
            }
        }
        __syncwarp();
        // small[j][(a*4+b)*4+d] = u_b[(a*4+d)] = G[:,kidx[b]] * invn[b]
        #pragma unroll
        for (int t = 0; t < 2; t++) {
            int e = lane + 32 * t;
            int d = e & 3, b = (e >> 2) & 3, a = e >> 4;
            s->small[j * 64 + e] = G[s->kidx[b] * 20 + (a * 4 + d)] * s->invn[b];
        }
        __syncwarp();
        // sv[b, r] = invn[b] * sum_row G[row, kidx[b]] m[row, r] = u_b^T m
        #pragma unroll
        for (int t = 0; t < 2; t++) {
            int e = lane + 32 * t; int r = e & 15, b = e >> 4;
            int ci = s->kidx[b];
            float acc = 0.f;
            #pragma unroll
            for (int row = 0; row < 16; row++) acc += G[ci * 20 + row] * m[row * 20 + r];
            sv[e] = acc * s->invn[b];
        }
        __syncwarp();
    }
    // site 9
    stage(s, peps, i, 9, lane); __syncwarp();
    absorb9<TOP>(s, lane); __syncwarp();
    if (lane < 16) {
        int d = lane & 3, a = lane >> 2;
        float acc = 0.f;
        #pragma unroll
        for (int b = 0; b < 16; b++) acc += sv[a * 16 + b] * s->M[b * 4 + d];
        s->small[9 * 64 + lane] = acc;
    }
    __syncwarp();
    // ---- Phase C: normalize + logn (guarded) ----
    float lacc = 0.f;
    for (int js = 0; js < 10; js++) {
        int n = (js == 0 || js == 9) ? 16 : 64;
        float ss = 0.f;
        for (int e = lane; e < n; e += 32) { float v = s->small[js * 64 + e]; ss += v * v; }
        ss = wsum(ss);
        float nrm = sqrtf(ss);
        float inv = (nrm > 1e-38f) ? (1.f / nrm) : 0.f;
        for (int e = lane; e < n; e += 32) s->small[js * 64 + e] *= inv;
        lacc += logf(fmaxf(nrm, 1e-38f));
    }
    if (lane == 0) s->logn += lacc;
    __syncwarp();
}

extern __shared__ float smraw[];

__global__ void __launch_bounds__(32)
amp_kernel(const int* __restrict__ x, const float* __restrict__ peps, float* __restrict__ out) {
    SM* s = (SM*)smraw;
    int lane = threadIdx.x;
    int blk = blockIdx.x;
    for (int e = lane; e < 100; e += 32) s->xr[e] = x[blk * 100 + e];
    if (lane == 0) s->logn = 0.f;
    __syncwarp();

    initRow<false>(s, peps, 0, lane);
    for (int i = 1; i <= 4; i++) compress<false>(s, peps, i, lane);
    // bottom compressed MPS -> registers
    float br[20];
    #pragma unroll
    for (int t = 0; t < 20; t++) br[t] = s->small[lane + 32 * t];
    __syncwarp();

    initRow<true>(s, peps, 9, lane);
    for (int i = 8; i >= 5; i--) compress<true>(s, peps, i, lane);

    // dump bottom MPS into the (dead) arena for the zip
    float* botS = s->A;
    #pragma unroll
    for (int t = 0; t < 20; t++) botS[lane + 32 * t] = br[t];
    __syncwarp();

    // ---- zip ----
    if (lane < 16) {
        int c = lane >> 2, e2 = lane & 3;
        float acc = 0.f;
        #pragma unroll
        for (int d = 0; d < 4; d++) acc += botS[c * 4 + d] * s->small[e2 * 4 + d];
        s->Eb[lane] = acc;
    }
    __syncwarp();
    for (int j = 1; j <= 8; j++) {
        if (lane < 16) {
            int c = lane >> 2, e2 = lane & 3;
            float acc = 0.f;
            #pragma unroll
            for (int a = 0; a < 4; a++)
                #pragma unroll
                for (int b = 0; b < 4; b++) {
                    float ev = s->Eb[a * 4 + b];
                    float dot = 0.f;
                    #pragma unroll
                    for (int d = 0; d < 4; d++)
                        dot += botS[j * 64 + (a * 4 + c) * 4 + d]
                             * s->small[j * 64 + (b * 4 + e2) * 4 + d];
                    acc += ev * dot;
                }
            s->Eb2[lane] = acc;
        }
        __syncwarp();
        if (lane < 16) s->Eb[lane] = s->Eb2[lane];
        __syncwarp();
    }
    float part = 0.f;
    if (lane < 16) {
        int a = lane >> 2, b = lane & 3;
        float dot = 0.f;
        #pragma unroll
        for (int d = 0; d < 4; d++)
            dot += botS[9 * 64 + a * 4 + d] * s->small[9 * 64 + b * 4 + d];
        part = s->Eb[a * 4 + b] * dot;
    }
    part = wsum(part);
    if (lane == 0) out[blk] = part * expf(s->logn);
}

extern "C" void kernel_launch(void* const* d_in, const int* in_sizes, int n_in,
                              void* d_out, int out_size) {
    const int* x;
    const float* peps;
    if (in_sizes[0] == 51200 && n_in >= 2) {
        peps = (const float*)d_in[0];
        x = (const int*)d_in[1];
    } else {
        x = (const int*)d_in[0];
        peps = (const float*)d_in[1];
    }
    float* out = (float*)d_out;
    cudaFuncSetAttribute(amp_kernel, cudaFuncAttributeMaxDynamicSharedMemorySize, (int)sizeof(SM));
    amp_kernel<<<out_size, 32, sizeof(SM)>>>(x, peps, out);
}